// round 13
// baseline (speedup 1.0000x reference)
#include <cuda_runtime.h>
#include <math.h>
#include <stdint.h>

#define Bq   8
#define Nq   1024
#define Hq   200
#define BNr  (Bq*Nq)
#define NCH  8
// plane sizes (elems)
#define PH   1638400L
#define PN   8388608L
#define PW   800000L
#define SNH  204800L
#define SNN  1048576L
// pipeline
#define STG     4
#define STGB    24576
#define OFF_AL  8192
#define OFF_BH  16384
#define OFF_BL  20480

// ---------------- scratch (no allocs allowed) ----------------
__device__ __align__(16) uint16_t g_outs [2*PH];
__device__ __align__(16) uint16_t g_outp [2*PH];
__device__ __align__(16) uint16_t g_bufA [2*PH];
__device__ __align__(16) uint16_t g_bufB [2*PH];
__device__ __align__(16) uint16_t g_bufC [2*PH];
__device__ __align__(16) uint16_t g_sc   [2*PN];
__device__ __align__(16) uint16_t g_scT  [2*PN];
__device__ __align__(16) uint16_t g_adj  [2*PN];
__device__ __align__(16) uint16_t g_wsp  [2*PW];
__device__ float g_denom[BNr];
__device__ float g_rmax [BNr];
__device__ float g_rsum [BNr];
__device__ float g_cmax [BNr];
__device__ float g_csum [BNr];
__device__ float g_pmax [NCH*BNr];
__device__ float g_psum [NCH*BNr];

// ---------------- helpers ----------------
__device__ __forceinline__ float warp_red_sum(float v){
#pragma unroll
    for (int o=16;o;o>>=1) v += __shfl_xor_sync(0xffffffffu, v, o);
    return v;
}
__device__ __forceinline__ float warp_red_max(float v){
#pragma unroll
    for (int o=16;o;o>>=1) v = fmaxf(v, __shfl_xor_sync(0xffffffffu, v, o));
    return v;
}
__device__ __forceinline__ uint32_t s2u(const void* p){
    uint32_t a;
    asm("{ .reg .u64 t; cvta.to.shared.u64 t, %1; cvt.u32.u64 %0, t; }" : "=r"(a) : "l"(p));
    return a;
}
__device__ __forceinline__ float bfv(uint16_t u){ return __uint_as_float(((uint32_t)u)<<16); }
__device__ __forceinline__ uint16_t bf1(float x){
    uint16_t r;
    asm("cvt.rn.bf16.f32 %0, %1;" : "=h"(r) : "f"(x));
    return r;
}
__device__ __forceinline__ float brd(const uint16_t* h, long pl, long i){
    return bfv(h[i]) + bfv(h[pl+i]);
}
__device__ __forceinline__ void bwr(uint16_t* h, long pl, long i, float x){
    uint16_t a = bf1(x);
    h[i] = a;
    h[pl+i] = bf1(x - bfv(a));
}
__device__ __forceinline__ void ldmx4(uint32_t* r, uint32_t addr){
    asm volatile("ldmatrix.sync.aligned.m8n8.x4.shared.b16 {%0,%1,%2,%3}, [%4];"
        : "=r"(r[0]),"=r"(r[1]),"=r"(r[2]),"=r"(r[3]) : "r"(addr));
}
__device__ __forceinline__ void ldmx4t(uint32_t* r, uint32_t addr){
    asm volatile("ldmatrix.sync.aligned.m8n8.x4.trans.shared.b16 {%0,%1,%2,%3}, [%4];"
        : "=r"(r[0]),"=r"(r[1]),"=r"(r[2]),"=r"(r[3]) : "r"(addr));
}
__device__ __forceinline__ void mma16(float* d, const uint32_t* a, const uint32_t* b){
    asm volatile("mma.sync.aligned.m16n8k16.row.col.f32.bf16.bf16.f32 "
        "{%0,%1,%2,%3}, {%4,%5,%6,%7}, {%8,%9}, {%0,%1,%2,%3};"
        : "+f"(d[0]),"+f"(d[1]),"+f"(d[2]),"+f"(d[3])
        : "r"(a[0]),"r"(a[1]),"r"(a[2]),"r"(a[3]), "r"(b[0]),"r"(b[1]));
}
__device__ __forceinline__ void cpa(uint32_t dst, const void* src, int sz){
    asm volatile("cp.async.cg.shared.global [%0], [%1], 16, %2;"
        :: "r"(dst), "l"(src), "r"(sz));
}
__device__ __forceinline__ int swz4(int row){ return ((row>>1) ^ (row>>3)) & 3; }

// ---------------- bf16x3 GEMM on split planes, cp.async 4-stage ----------------
// Inputs: A hi plane + lo at +pA (K-major [M,K], lda elems).
// B: BT=1: [N,K] K-major (non-trans ldmatrix); BT=0: [K,N] (trans ldmatrix).
// C written split (hi + lo at +pC). res split (+pR).
// EPI: 0 +bias(opt); 1 +bias+res; 2 gelu(+bias); 3 *scale+keymask(tm[gj]);
//      4 +pairmask; 5 relu(acc/st1[gi])+res; 6 acc*tm[gi]+res
// Requires M%128==0, Kd%8==0 && Kd>=96, Nc%8==0, base/lda/ldb 8-elem aligned.
template<int BT,int EPI>
__global__ void __launch_bounds__(256,2)
mma_k(const uint16_t* __restrict__ Ah, const uint16_t* __restrict__ Bh,
      uint16_t* __restrict__ Ch,
      int M, int Nc, int Kd, int lda, int ldb, int ldc,
      long sA_, long sB_, long sC_, long pA, long pB, long pC, long pR,
      const float* __restrict__ bias, const uint16_t* __restrict__ resh,
      const float* __restrict__ st1, const float* __restrict__ tm, float scale)
{
    extern __shared__ __align__(16) char smem[];
    const int b  = blockIdx.z;
    const int i0 = blockIdx.y*128, j0 = blockIdx.x*64;
    const int tid = threadIdx.x, lid = tid&31, wid = tid>>5;
    const int wm = wid&3, wn = wid>>2;
    const uint16_t* Ab = Ah + (long)b*sA_;
    const uint16_t* Bb = Bh + (long)b*sB_;
    const uint32_t sm0 = s2u(smem);

    float acc[2][4][4];
#pragma unroll
    for (int mt=0;mt<2;mt++)
#pragma unroll
        for (int nt=0;nt<4;nt++)
#pragma unroll
            for (int e=0;e<4;e++) acc[mt][nt][e]=0.f;

    auto issue = [&](int c){
        uint32_t sb = sm0 + (c % STG)*STGB;
        int k0 = c*32;
#pragma unroll
        for (int p=0;p<4;p++){
            int s = tid + p*256; int pl = s>>9, rem = s&511, row = rem>>2, g = rem&3;
            const uint16_t* src = Ab + (long)pl*pA + (long)(i0+row)*lda + k0 + g*8;
            uint32_t dst = sb + pl*OFF_AL + row*64 + (((g ^ swz4(row))&3)<<4);
            cpa(dst, src, (k0+g*8 < Kd) ? 16 : 0);
        }
        if (BT==1){
#pragma unroll
            for (int p=0;p<2;p++){
                int s = tid + p*256; int pl = s>>8, rem = s&255, row = rem>>2, g = rem&3;
                const uint16_t* src = Bb + (long)pl*pB + (long)(j0+row)*ldb + k0 + g*8;
                uint32_t dst = sb + OFF_BH + pl*4096 + row*64 + (((g ^ swz4(row))&3)<<4);
                cpa(dst, src, (j0+row < Nc && k0+g*8 < Kd) ? 16 : 0);
            }
        } else {
#pragma unroll
            for (int p=0;p<2;p++){
                int s = tid + p*256; int pl = s>>8, rem = s&255, k = rem>>3, g = rem&7;
                const uint16_t* src = Bb + (long)pl*pB + (long)(k0+k)*ldb + j0 + g*8;
                uint32_t dst = sb + OFF_BH + pl*4096 + k*128 + (((g ^ (k&7))&7)<<4);
                cpa(dst, src, (k0+k < Kd && j0+g*8 < Nc) ? 16 : 0);
            }
        }
        asm volatile("cp.async.commit_group;");
    };

    // per-lane fragment constants
    int arow[2], aswz[2];
#pragma unroll
    for (int mt=0;mt<2;mt++){
        arow[mt] = wm*32 + mt*16 + (lid&7) + ((lid>>3)&1)*8;
        aswz[mt] = swz4(arow[mt]);
    }
    const int akg = lid>>4;
    int brow[2], bswz[2];
#pragma unroll
    for (int jp=0;jp<2;jp++){
        brow[jp] = wn*32 + jp*16 + ((lid>>4)&1)*8 + (lid&7);
        bswz[jp] = swz4(brow[jp]);
    }
    const int bkg = (lid>>3)&1;
    const int tkrow = (lid&7) + ((lid>>3)&1)*8;   // BT=0 trans k-row base
    const int tng  = wn*4 + (lid>>4);             // BT=0 n-group base (+jp*2)

    const int nch = (Kd + 31) >> 5;
    issue(0); issue(1); issue(2);
    for (int c=0; c<nch; c++){
        asm volatile("cp.async.wait_group 2;");
        __syncthreads();
        const uint32_t sb = sm0 + (c % STG)*STGB;
#pragma unroll
        for (int ks=0; ks<2; ks++){
            uint32_t af[2][2][4], bf2[2][2][4];
#pragma unroll
            for (int mt=0;mt<2;mt++){
                uint32_t aoff = (uint32_t)(arow[mt]*64 + ((((2*ks+akg) ^ aswz[mt])&3)<<4));
                ldmx4(af[mt][0], sb + aoff);
                ldmx4(af[mt][1], sb + OFF_AL + aoff);
            }
            if (BT==1){
#pragma unroll
                for (int jp=0;jp<2;jp++){
                    uint32_t boff = (uint32_t)(brow[jp]*64 + ((((2*ks+bkg) ^ bswz[jp])&3)<<4));
                    ldmx4(bf2[jp][0], sb + OFF_BH + boff);
                    ldmx4(bf2[jp][1], sb + OFF_BL + boff);
                }
            } else {
#pragma unroll
                for (int jp=0;jp<2;jp++){
                    int krow = ks*16 + tkrow;
                    int ngrp = tng + jp*2;
                    uint32_t boff = (uint32_t)(krow*128 + (((ngrp ^ (krow&7))&7)<<4));
                    ldmx4t(bf2[jp][0], sb + OFF_BH + boff);
                    ldmx4t(bf2[jp][1], sb + OFF_BL + boff);
                }
            }
#pragma unroll
            for (int mt=0;mt<2;mt++)
#pragma unroll
                for (int nt=0;nt<4;nt++){
                    float* d = acc[mt][nt];
                    const uint32_t* bh = &bf2[nt>>1][0][(nt&1)*2];
                    const uint32_t* bl = &bf2[nt>>1][1][(nt&1)*2];
                    mma16(d, af[mt][1], bh);   // lo*hi
                    mma16(d, af[mt][0], bl);   // hi*lo
                    mma16(d, af[mt][0], bh);   // hi*hi
                }
        }
        if (c+STG-1 < nch) issue(c+STG-1);
        else asm volatile("cp.async.commit_group;");
    }

    // ---- epilogue ----
    uint16_t* Cl = Ch + pC;
#pragma unroll
    for (int mt=0;mt<2;mt++){
        int gmr = i0 + wm*32 + mt*16 + (lid>>2);
#pragma unroll
        for (int nt=0;nt<4;nt++){
            int gn0 = j0 + wn*32 + nt*8 + (lid&3)*2;
#pragma unroll
            for (int e=0;e<4;e++){
                int gi = gmr + (e>>1)*8;
                int gj = gn0 + (e&1);
                if (gj >= Nc) continue;
                float v = acc[mt][nt][e];
                long cidx = (long)b*sC_ + (long)gi*ldc + gj;
                if (EPI==0){ if (bias) v += bias[gj]; }
                else if (EPI==1){ v += bias[gj]; v += brd(resh, pR, cidx); }
                else if (EPI==2){ v += bias[gj]; v = 0.5f*v*(1.f+erff(v*0.70710678f)); }
                else if (EPI==3){ v = v*scale + (tm[b*Nq+gj]-1.f)*10000.f; }
                else if (EPI==4){ v = v + (tm[b*Nq+gi]*tm[b*Nq+gj]-1.f)*10000.f; }
                else if (EPI==5){ v = fmaxf(v/st1[b*M+gi], 0.f) + brd(resh, pR, cidx); }
                else if (EPI==6){ v = v*tm[b*Nq+gi] + brd(resh, pR, cidx); }
                uint16_t hv = bf1(v);
                Ch[cidx] = hv;
                Cl[cidx] = bf1(v - bfv(hv));
            }
        }
    }
}

// ---------------- softmax / stats (split buffers) ----------------
template<bool WRITE>
__global__ void __launch_bounds__(256)
softmax_row_k(uint16_t* __restrict__ S, float* __restrict__ rmax, float* __restrict__ rsum){
    long row = blockIdx.x;
    long base = row*(long)Nq;
    int t = threadIdx.x;
    float v[4];
    float mx = -1e30f;
#pragma unroll
    for (int l=0;l<4;l++){ v[l]=brd(S, PN, base + t + l*256); mx=fmaxf(mx,v[l]); }
    __shared__ float sm[8];
    mx = warp_red_max(mx);
    if ((t&31)==0) sm[t>>5]=mx;
    __syncthreads();
    float m2 = sm[0];
#pragma unroll
    for (int w=1;w<8;w++) m2 = fmaxf(m2, sm[w]);
    float s = 0.f;
#pragma unroll
    for (int l=0;l<4;l++){ v[l]=__expf(v[l]-m2); s+=v[l]; }
    __syncthreads();
    s = warp_red_sum(s);
    if ((t&31)==0) sm[t>>5]=s;
    __syncthreads();
    float st = 0.f;
#pragma unroll
    for (int w=0;w<8;w++) st += sm[w];
    if (WRITE){
        float inv = 1.f/st;
#pragma unroll
        for (int l=0;l<4;l++) bwr(S, PN, base + t + l*256, v[l]*inv);
    } else if (t==0){ rmax[row]=m2; rsum[row]=st; }
}

__global__ void __launch_bounds__(256)
colstats_part(const uint16_t* __restrict__ L, float* __restrict__ pmax, float* __restrict__ psum){
    int g  = blockIdx.x*256 + threadIdx.x;
    int ch = blockIdx.y;
    int b = g >> 10, m = g & 1023;
    long base = (long)b*SNN + m + (long)ch*(Nq/NCH)*Nq;
    float mx=-1e30f, s=0.f;
#pragma unroll 4
    for (int n=0;n<Nq/NCH;n++){
        float x = brd(L, PN, base + (long)n*Nq);
        if (x>mx){ s = s*__expf(mx-x) + 1.f; mx = x; }
        else       s += __expf(x-mx);
    }
    pmax[ch*BNr+g]=mx; psum[ch*BNr+g]=s;
}
__global__ void __launch_bounds__(256)
colstats_comb(const float* __restrict__ pmax, const float* __restrict__ psum,
              float* __restrict__ cmax, float* __restrict__ csum){
    int g = blockIdx.x*256 + threadIdx.x;
    float mx=-1e30f, s=0.f;
#pragma unroll
    for (int ch=0; ch<NCH; ch++){
        float m2=pmax[ch*BNr+g], s2=psum[ch*BNr+g];
        if (m2>mx){ s = s*__expf(mx-m2) + s2; mx = m2; }
        else        s += s2*__expf(m2-mx);
    }
    cmax[g]=mx; csum[g]=s;
}

// ---------------- dual normalize: P_row in place, P_col^T transposed ----------------
__global__ void __launch_bounds__(256)
normalize_dual(uint16_t* __restrict__ L, uint16_t* __restrict__ LT,
               const float* __restrict__ rmax, const float* __restrict__ rsum,
               const float* __restrict__ cmax, const float* __restrict__ csum){
    __shared__ float sm[32][33];
    int b = blockIdx.z;
    int i0 = blockIdx.y*32, j0 = blockIdx.x*32;
    int tx = threadIdx.x & 31, ty = threadIdx.x >> 5;
    long Lb = (long)b*SNN;
    int gb = b*Nq;
#pragma unroll
    for (int p=0;p<4;p++){
        int ti = ty + p*8;
        int gi = i0+ti, gj = j0+tx;
        long idx = Lb + (long)gi*Nq + gj;
        float l = brd(L, PN, idx);
        bwr(L, PN, idx, __expf(l - rmax[gb+gi]) / rsum[gb+gi]);
        sm[ti][tx] = __expf(l - cmax[gb+gj]) / csum[gb+gj];
    }
    __syncthreads();
#pragma unroll
    for (int p=0;p<4;p++){
        int tj = ty + p*8;
        bwr(LT, PN, Lb + (long)(j0+tj)*Nq + i0 + tx, sm[tx][tj]);
    }
}

// ---------------- layernorm (1 warp / row, H=200, split in/out) ----------------
__global__ void __launch_bounds__(32)
ln_k(const uint16_t* __restrict__ X, const float* __restrict__ g,
     const float* __restrict__ bt, uint16_t* __restrict__ Y){
    long row = blockIdx.x;
    long base = row*(long)Hq;
    int t = threadIdx.x;
    float v[7]; float s=0.f;
#pragma unroll
    for (int l=0;l<7;l++){ int c=t+l*32; v[l]=(c<Hq)?brd(X, PH, base+c):0.f; s+=v[l]; }
    s = warp_red_sum(s);
    float mu = s*(1.f/Hq);
    float var = 0.f;
#pragma unroll
    for (int l=0;l<7;l++){ int c=t+l*32; if (c<Hq){ float d=v[l]-mu; var+=d*d; } }
    var = warp_red_sum(var)*(1.f/Hq);
    float r = rsqrtf(var + 1e-20f);
#pragma unroll
    for (int l=0;l<7;l++){ int c=t+l*32; if (c<Hq) bwr(Y, PH, base+c, (v[l]-mu)*r*g[c]+bt[c]); }
}

// ---------------- adj + denom (fp32 out + split scratch) ----------------
__global__ void __launch_bounds__(256)
adj_k(const float* __restrict__ a1, const float* __restrict__ a2,
      float* __restrict__ adjo, uint16_t* __restrict__ adjs, float* __restrict__ den){
    long row = blockIdx.x;
    long base = row*(long)Nq;
    int t = threadIdx.x;
    float s = 0.f;
#pragma unroll
    for (int l=0;l<4;l++){
        long m = base + t + l*256;
        float v = fminf(a1[m]+a2[m], 1.f);
        adjo[m]=v; bwr(adjs, PN, m, v); s+=v;
    }
    __shared__ float sm[8];
    s = warp_red_sum(s);
    if ((t&31)==0) sm[t>>5]=s;
    __syncthreads();
    if (t==0){
        float tot=0.f;
#pragma unroll
        for (int w=0;w<8;w++) tot+=sm[w];
        den[row]=tot+1e-7f;
    }
}

__global__ void init_k(const float* __restrict__ text, uint16_t* __restrict__ o1, uint16_t* __restrict__ o2){
    for (long i = blockIdx.x*256L + threadIdx.x; i < PH; i += (long)gridDim.x*256){
        float v = text[i];
        bwr(o1, PH, i, v); bwr(o2, PH, i, v);
    }
}
__global__ void fin_k(const uint16_t* __restrict__ h, float* __restrict__ o){
    long i = blockIdx.x*256L + threadIdx.x;
    if (i < PH) o[i] = brd(h, PH, i);
}
__global__ void wsplit_k(const float* qw, const float* kw, const float* vw, const float* aw,
                         const float* iw, const float* ow, const float* gw, const float* mw,
                         uint16_t* wh){
    for (long i = blockIdx.x*256L + threadIdx.x; i < PW; i += (long)gridDim.x*256){
        float x;
        if      (i < 120000) x = qw[i];
        else if (i < 240000) x = kw[i-120000];
        else if (i < 360000) x = vw[i-240000];
        else if (i < 480000) x = aw[i-360000];
        else if (i < 600000) x = iw[i-480000];
        else if (i < 720000) x = ow[i-600000];
        else if (i < 760000) x = gw[i-720000];
        else                 x = mw[i-760000];
        bwr(wh, PW, i, x);
    }
}

// ---------------- host-side GEMM launcher ----------------
template<int BT,int EPI>
static void MG(const uint16_t*Ah,const uint16_t*Bh,uint16_t*Ch,
               int M,int Nc,int Kd,int lda,int ldb,int ldc,
               long sa,long sb,long sc_,long pA,long pB,long pC,int batch,
               const float*bias,const uint16_t*resh,long pR,
               const float*st1,const float*tmv,float scale){
    cudaFuncSetAttribute(mma_k<BT,EPI>, cudaFuncAttributeMaxDynamicSharedMemorySize, STG*STGB);
    dim3 grid((Nc+63)/64, M/128, batch);
    mma_k<BT,EPI><<<grid,256,STG*STGB>>>(Ah,Bh,Ch,M,Nc,Kd,lda,ldb,ldc,
                                         sa,sb,sc_,pA,pB,pC,pR,bias,resh,st1,tmv,scale);
}

extern "C" void kernel_launch(void* const* d_in, const int* in_sizes, int n_in,
                              void* d_out, int out_size)
{
    const float* text  = (const float*)d_in[0];
    const float* adj1  = (const float*)d_in[1];
    const float* adj2  = (const float*)d_in[2];
    const float* tmask = (const float*)d_in[5];
    const float* gcn_w = (const float*)d_in[6];
    const float* mut_w = (const float*)d_in[7];
    const float* qw=(const float*)d_in[8],  *qb=(const float*)d_in[9];
    const float* kw=(const float*)d_in[10], *kb=(const float*)d_in[11];
    const float* vw=(const float*)d_in[12], *vb=(const float*)d_in[13];
    const float* aw=(const float*)d_in[14], *ab=(const float*)d_in[15];
    const float* g1=(const float*)d_in[16], *b1=(const float*)d_in[17];
    const float* iw=(const float*)d_in[18], *ib=(const float*)d_in[19];
    const float* ow=(const float*)d_in[20], *ob=(const float*)d_in[21];
    const float* g2=(const float*)d_in[22], *b2=(const float*)d_in[23];

    float* out  = (float*)d_out;
    float* adjo = out + PH;               // adj output region

    void* p;
    cudaGetSymbolAddress(&p, g_outs);  uint16_t* outs=(uint16_t*)p;
    cudaGetSymbolAddress(&p, g_outp);  uint16_t* outp=(uint16_t*)p;
    cudaGetSymbolAddress(&p, g_bufA);  uint16_t* bA=(uint16_t*)p;
    cudaGetSymbolAddress(&p, g_bufB);  uint16_t* bB=(uint16_t*)p;
    cudaGetSymbolAddress(&p, g_bufC);  uint16_t* bC=(uint16_t*)p;
    cudaGetSymbolAddress(&p, g_sc);    uint16_t* sc=(uint16_t*)p;
    cudaGetSymbolAddress(&p, g_scT);   uint16_t* scT=(uint16_t*)p;
    cudaGetSymbolAddress(&p, g_adj);   uint16_t* adjs=(uint16_t*)p;
    cudaGetSymbolAddress(&p, g_wsp);   uint16_t* wh=(uint16_t*)p;
    cudaGetSymbolAddress(&p, g_denom); float* den=(float*)p;
    cudaGetSymbolAddress(&p, g_rmax);  float* rmax=(float*)p;
    cudaGetSymbolAddress(&p, g_rsum);  float* rsum=(float*)p;
    cudaGetSymbolAddress(&p, g_cmax);  float* cmax=(float*)p;
    cudaGetSymbolAddress(&p, g_csum);  float* csum=(float*)p;
    cudaGetSymbolAddress(&p, g_pmax);  float* pmax=(float*)p;
    cudaGetSymbolAddress(&p, g_psum);  float* psum=(float*)p;

    const float rscale = 1.0f/sqrtf((float)Hq);

    init_k<<<640,256>>>(text, outs, outp);
    adj_k<<<BNr,256>>>(adj1, adj2, adjo, adjs, den);
    wsplit_k<<<640,256>>>(qw,kw,vw,aw,iw,ow,gcn_w,mut_w, wh);

    for (int i=0;i<3;i++){
        const uint16_t *wq = wh +      0 + (long)i*40000;
        const uint16_t *wk = wh + 120000 + (long)i*40000;
        const uint16_t *wv = wh + 240000 + (long)i*40000;
        const uint16_t *wa = wh + 360000 + (long)i*40000;
        const uint16_t *wi = wh + 480000 + (long)i*40000;
        const uint16_t *wo = wh + 600000 + (long)i*40000;
        const uint16_t *wg = wh + 720000;
        const uint16_t *wm = wh + 760000;
        const float *qbi=qb+i*Hq, *kbi=kb+i*Hq, *vbi=vb+i*Hq, *abi=ab+i*Hq;
        const float *ibi=ib+i*Hq, *obi=ob+i*Hq;
        const float *g1i=g1+i*Hq, *b1i=b1+i*Hq, *g2i=g2+i*Hq, *b2i=b2+i*Hq;

        // ---- BERT layer ----
        MG<0,0>(outs,wq,bA, 8192,Hq,Hq, Hq,Hq,Hq, 0,0,0, PH,PW,PH, 1, qbi,0,0, 0,0,0.f);  // q
        MG<0,0>(outs,wk,bB, 8192,Hq,Hq, Hq,Hq,Hq, 0,0,0, PH,PW,PH, 1, kbi,0,0, 0,0,0.f);  // k
        MG<0,0>(outs,wv,bC, 8192,Hq,Hq, Hq,Hq,Hq, 0,0,0, PH,PW,PH, 1, vbi,0,0, 0,0,0.f);  // v
        MG<1,3>(bA,bB,sc, Nq,Nq,Hq, Hq,Hq,Nq, SNH,SNH,SNN, PH,PH,PN, Bq, 0,0,0, 0, tmask, rscale); // scores
        softmax_row_k<true><<<BNr,256>>>(sc, 0, 0);
        MG<0,0>(sc,bC,bA, Nq,Hq,Nq, Nq,Hq,Hq, SNN,SNH,SNH, PN,PH,PH, Bq, 0,0,0, 0,0,0.f); // ctx
        MG<0,1>(bA,wa,bB, 8192,Hq,Hq, Hq,Hq,Hq, 0,0,0, PH,PW,PH, 1, abi, outs, PH, 0,0,0.f); // pre-LN1
        ln_k<<<BNr,32>>>(bB, g1i, b1i, bC);                                                // attn
        MG<0,2>(bC,wi,bA, 8192,Hq,Hq, Hq,Hq,Hq, 0,0,0, PH,PW,PH, 1, ibi,0,0, 0,0,0.f);    // inter (gelu)
        MG<0,1>(bA,wo,bB, 8192,Hq,Hq, Hq,Hq,Hq, 0,0,0, PH,PW,PH, 1, obi, bC, PH, 0,0,0.f); // pre-LN2
        ln_k<<<BNr,32>>>(bB, g2i, b2i, outs);                                              // outs updated

        // ---- GCN propagation ----
        MG<0,0>(outp,wg,bA, 8192,Hq,Hq, Hq,Hq,Hq, 0,0,0, PH,PW,PH, 1, 0,0,0, 0,0,0.f);    // teout
        MG<0,5>(adjs,bA,bB, Nq,Hq,Nq, Nq,Hq,Hq, SNN,SNH,SNH, PN,PH,PH, Bq, 0, outp, PH, den, 0, 0.f);
        { uint16_t* t_=outp; outp=bB; bB=t_; }

        // ---- self-alignment ----
        MG<0,0>(outs,wm,bA, 8192,Hq,Hq, Hq,Hq,Hq, 0,0,0, PH,PW,PH, 1, 0,0,0, 0,0,0.f);    // mo
        MG<1,4>(bA,outp,sc, Nq,Nq,Hq, Hq,Hq,Nq, SNH,SNH,SNN, PH,PH,PN, Bq, 0,0,0, 0, tmask, 0.f); // logit
        softmax_row_k<false><<<BNr,256>>>(sc, rmax, rsum);
        colstats_part<<<dim3(BNr/256,NCH),256>>>(sc, pmax, psum);
        colstats_comb<<<BNr/256,256>>>(pmax, psum, cmax, csum);
        normalize_dual<<<dim3(Nq/32,Nq/32,Bq),256>>>(sc, scT, rmax, rsum, cmax, csum);
        MG<0,6>(sc,  outp, bC, Nq,Hq,Nq, Nq,Hq,Hq, SNN,SNH,SNH, PN,PH,PH, Bq, 0, outs, PH, 0, tmask, 0.f);
        MG<0,6>(scT, outs, bB, Nq,Hq,Nq, Nq,Hq,Hq, SNN,SNH,SNH, PN,PH,PH, Bq, 0, outp, PH, 0, tmask, 0.f);
        { uint16_t* t_=outs; outs=bC; bC=t_; }
        { uint16_t* t_=outp; outp=bB; bB=t_; }
    }

    fin_k<<<(PH+255)/256,256>>>(outs, out);
}

// round 14
// speedup vs baseline: 1.0717x; 1.0717x over previous
#include <cuda_runtime.h>
#include <math.h>
#include <stdint.h>

#define Bq   8
#define Nq   1024
#define Hq   200
#define BNr  (Bq*Nq)
#define NCH  8
#define LQ   608

// ---------------- scratch (no allocs allowed) ----------------
__device__ float g_outs  [BNr*Hq];
__device__ float g_output[BNr*Hq];
__device__ float g_bufA  [BNr*Hq];
__device__ float g_bufB  [BNr*Hq];
__device__ float g_bufC  [BNr*Hq];
__device__ float g_scores[Bq*Nq*Nq];
__device__ float g_scT   [Bq*Nq*Nq];
__device__ float g_qkv   [(long)BNr*LQ];
__device__ float g_wqkv  [3L*Hq*LQ];
__device__ float g_bqkv  [3*LQ];
__device__ float g_denom [BNr];
__device__ float g_rmax  [BNr];
__device__ float g_rsum  [BNr];
__device__ float g_cmax  [BNr];
__device__ float g_csum  [BNr];
__device__ float g_pmax  [NCH*BNr];
__device__ float g_psum  [NCH*BNr];

// ---------------- generic helpers ----------------
__device__ __forceinline__ float warp_red_sum(float v){
#pragma unroll
    for (int o=16;o;o>>=1) v += __shfl_xor_sync(0xffffffffu, v, o);
    return v;
}
__device__ __forceinline__ float warp_red_max(float v){
#pragma unroll
    for (int o=16;o;o>>=1) v = fmaxf(v, __shfl_xor_sync(0xffffffffu, v, o));
    return v;
}

// ---------------- tensor-core primitives (baseline PTX, no 'a' features) ----------------
__device__ __forceinline__ uint32_t s2u(const void* p){
    uint32_t a;
    asm("{ .reg .u64 t; cvta.to.shared.u64 t, %1; cvt.u32.u64 %0, t; }" : "=r"(a) : "l"(p));
    return a;
}
__device__ __forceinline__ uint32_t bfp(float x0, float x1){
    uint32_t r;
    asm("cvt.rn.bf16x2.f32 %0, %1, %2;" : "=r"(r) : "f"(x1), "f"(x0));
    return r;
}
__device__ __forceinline__ float blo(uint32_t h){ return __uint_as_float(h<<16); }
__device__ __forceinline__ float bhi(uint32_t h){ return __uint_as_float(h & 0xFFFF0000u); }
__device__ __forceinline__ uint16_t bf1(float x){
    uint16_t r;
    asm("cvt.rn.bf16.f32 %0, %1;" : "=h"(r) : "f"(x));
    return r;
}
__device__ __forceinline__ void ldmx4(uint32_t* r, uint32_t addr){
    asm volatile("ldmatrix.sync.aligned.m8n8.x4.shared.b16 {%0,%1,%2,%3}, [%4];"
        : "=r"(r[0]),"=r"(r[1]),"=r"(r[2]),"=r"(r[3]) : "r"(addr));
}
__device__ __forceinline__ void mma16(float* d, const uint32_t* a, const uint32_t* b){
    asm volatile("mma.sync.aligned.m16n8k16.row.col.f32.bf16.bf16.f32 "
        "{%0,%1,%2,%3}, {%4,%5,%6,%7}, {%8,%9}, {%0,%1,%2,%3};"
        : "+f"(d[0]),"+f"(d[1]),"+f"(d[2]),"+f"(d[3])
        : "r"(a[0]),"r"(a[1]),"r"(a[2]),"r"(a[3]), "r"(b[0]),"r"(b[1]));
}
__device__ __forceinline__ int swz4(int row){ return ((row>>1) ^ (row>>3)) & 3; }

// ---------------- mma.sync bf16x3 GEMM (error-compensated) ----------------
// C[b,i,j] = epi( sum_k A[b,i,k] * Bop[b,k,j] ), near-fp32 via
//   x = xh + xl (bf16 split), C += Ah*Bh + Ah*Bl + Al*Bh  (drop Al*Bl ~2^-16)
// BT: 0 = B stored [Kd, Nc'] row-major (transpose during smem staging)
//     1 = B stored [Nc', Kd] row-major (native K-major)
// EPI: 0 +bias(opt); 1 +bias+res; 2 gelu(+bias); 3 *scale+keymask(tm[gj]);
//      4 +pairmask; 5 relu(acc/st1[gi])+res; 6 acc*tm[gi]+res
// Requires M%128==0, Kd%4==0, lda/ldb%4==0, bases 16B-aligned.
template<int BT,int EPI>
__global__ void __launch_bounds__(256,2)
mma_k(const float* __restrict__ A, const float* __restrict__ Bm, float* __restrict__ C,
      int M, int Nc, int Kd, int lda, int ldb, int ldc,
      long sA_, long sB_, long sC_,
      const float* __restrict__ bias, const float* __restrict__ res,
      const float* __restrict__ st1, const float* __restrict__ tm, float scale)
{
    // bf16 planes: [buf][plane hi/lo][row*64B], K-chunk = 32 bf16 per row
    __shared__ __align__(16) char sAm[2][2][128*64];   // 32 KB
    __shared__ __align__(16) char sBm[2][2][64*64];    // 16 KB
    const int b  = blockIdx.z;
    const int i0 = blockIdx.y*128, j0 = blockIdx.x*64;
    const int tid = threadIdx.x, lid = tid&31, wid = tid>>5;
    const int wm = wid&3, wn = wid>>2;
    const float* Ab = A + (long)b*sA_;
    const float* Bb = Bm + (long)b*sB_;

    float acc[2][4][4];
#pragma unroll
    for (int mt=0;mt<2;mt++)
#pragma unroll
        for (int nt=0;nt<4;nt++)
#pragma unroll
            for (int e=0;e<4;e++) acc[mt][nt][e]=0.f;

    float4 ra[4];      // A staging: 128 rows x 32 k / 256 thr
    float4 rb1[2];     // B staging BT=1
    float4 rbt[2];     // B staging BT=0

    auto ldgA = [&](int k0){
#pragma unroll
        for (int p=0;p<4;p++){
            int s = tid + p*256; int row = s>>3, kq = s&7;
            int gk = k0 + kq*4;
            ra[p] = (gk+3 < Kd) ? *(const float4*)&Ab[(long)(i0+row)*lda + gk]
                                : make_float4(0.f,0.f,0.f,0.f);
        }
    };
    auto stsA = [&](int sel){
#pragma unroll
        for (int p=0;p<4;p++){
            int s = tid + p*256; int row = s>>3, kq = s&7;
            float4 v = ra[p];
            uint32_t h0 = bfp(v.x, v.y), h1 = bfp(v.z, v.w);
            uint32_t l0 = bfp(v.x - blo(h0), v.y - bhi(h0));
            uint32_t l1 = bfp(v.z - blo(h1), v.w - bhi(h1));
            int off = row*64 + ((((kq>>1) ^ swz4(row))&3)<<4) + (kq&1)*8;
            *(uint2*)(sAm[sel][0] + off) = make_uint2(h0, h1);
            *(uint2*)(sAm[sel][1] + off) = make_uint2(l0, l1);
        }
    };
    auto ldgB = [&](int k0){
        if (BT==1){
#pragma unroll
            for (int p=0;p<2;p++){
                int s = tid + p*256; int row = s>>3, kq = s&7;
                int gj = j0 + row, gk = k0 + kq*4;
                rb1[p] = (gj < Nc && gk+3 < Kd) ? *(const float4*)&Bb[(long)gj*ldb + gk]
                                                : make_float4(0.f,0.f,0.f,0.f);
            }
        } else {
            int n0 = (tid&7)*8, kk = tid>>3;
            int gk = k0 + kk;
            bool ko = gk < Kd;
            int gn = j0 + n0;
            rbt[0] = (ko && gn+3 < Nc) ? *(const float4*)&Bb[(long)gk*ldb + gn]
                                       : make_float4(0.f,0.f,0.f,0.f);
            rbt[1] = (ko && gn+7 < Nc) ? *(const float4*)&Bb[(long)gk*ldb + gn + 4]
                                       : make_float4(0.f,0.f,0.f,0.f);
        }
    };
    auto stsB = [&](int sel){
        if (BT==1){
#pragma unroll
            for (int p=0;p<2;p++){
                int s = tid + p*256; int row = s>>3, kq = s&7;
                float4 v = rb1[p];
                uint32_t h0 = bfp(v.x, v.y), h1 = bfp(v.z, v.w);
                uint32_t l0 = bfp(v.x - blo(h0), v.y - bhi(h0));
                uint32_t l1 = bfp(v.z - blo(h1), v.w - bhi(h1));
                int off = row*64 + ((((kq>>1) ^ swz4(row))&3)<<4) + (kq&1)*8;
                *(uint2*)(sBm[sel][0] + off) = make_uint2(h0, h1);
                *(uint2*)(sBm[sel][1] + off) = make_uint2(l0, l1);
            }
        } else {
            int n0 = (tid&7)*8, kk = tid>>3;   // kk in 0..31
            const float* pv = (const float*)rbt;
            int gbyte = ((kk*2)>>4);
            int ibyte = (kk*2)&15;
#pragma unroll
            for (int i=0;i<8;i++){
                int n = n0 + i;
                float x = pv[i];
                uint16_t h = bf1(x);
                float hf = __uint_as_float(((uint32_t)h)<<16);
                uint16_t l = bf1(x - hf);
                int off = n*64 + (((gbyte ^ swz4(n))&3)<<4) + ibyte;
                *(uint16_t*)(sBm[sel][0] + off) = h;
                *(uint16_t*)(sBm[sel][1] + off) = l;
            }
        }
    };

    // per-lane fragment constants
    int arow[2], aswz[2];
#pragma unroll
    for (int mt=0;mt<2;mt++){
        arow[mt] = wm*32 + mt*16 + (lid&7) + ((lid>>3)&1)*8;
        aswz[mt] = swz4(arow[mt]);
    }
    const int akg = lid>>4;
    int brow[2], bswz[2];
#pragma unroll
    for (int jp=0;jp<2;jp++){
        brow[jp] = wn*32 + jp*16 + ((lid>>4)&1)*8 + (lid&7);
        bswz[jp] = swz4(brow[jp]);
    }
    const int bkg = (lid>>3)&1;
    uint32_t aB[2][2], bB[2][2];
#pragma unroll
    for (int s=0;s<2;s++)
#pragma unroll
        for (int pl=0;pl<2;pl++){
            aB[s][pl] = s2u(sAm[s][pl]);
            bB[s][pl] = s2u(sBm[s][pl]);
        }

    const int nch = (Kd + 31) >> 5;
    ldgA(0); ldgB(0);
    stsA(0); stsB(0);
    for (int c=0; c<nch; c++){
        __syncthreads();
        if (c+1 < nch){ ldgA((c+1)*32); ldgB((c+1)*32); }
        const int sel = c & 1;
#pragma unroll
        for (int ks=0; ks<2; ks++){
            uint32_t aoff[2], boff[2];
            uint32_t afh[2][4], afl[2][4], bfh[2][4], bfl[2][4];
            // hi fragments
#pragma unroll
            for (int mt=0;mt<2;mt++){
                aoff[mt] = (uint32_t)(arow[mt]*64 + ((((2*ks+akg) ^ aswz[mt])&3)<<4));
                ldmx4(afh[mt], aB[sel][0] + aoff[mt]);
            }
#pragma unroll
            for (int jp=0;jp<2;jp++){
                boff[jp] = (uint32_t)(brow[jp]*64 + ((((2*ks+bkg) ^ bswz[jp])&3)<<4));
                ldmx4(bfh[jp], bB[sel][0] + boff[jp]);
            }
            // hi*hi while lo fragments load
#pragma unroll
            for (int mt=0;mt<2;mt++)
#pragma unroll
                for (int nt=0;nt<4;nt++)
                    mma16(acc[mt][nt], afh[mt], &bfh[nt>>1][(nt&1)*2]);
#pragma unroll
            for (int mt=0;mt<2;mt++) ldmx4(afl[mt], aB[sel][1] + aoff[mt]);
#pragma unroll
            for (int jp=0;jp<2;jp++) ldmx4(bfl[jp], bB[sel][1] + boff[jp]);
            // cross terms
#pragma unroll
            for (int mt=0;mt<2;mt++)
#pragma unroll
                for (int nt=0;nt<4;nt++){
                    mma16(acc[mt][nt], afh[mt], &bfl[nt>>1][(nt&1)*2]);
                    mma16(acc[mt][nt], afl[mt], &bfh[nt>>1][(nt&1)*2]);
                }
        }
        if (c+1 < nch){ stsA((c+1)&1); stsB((c+1)&1); }
    }

    // ---- epilogue ----
#pragma unroll
    for (int mt=0;mt<2;mt++){
        int gmr = i0 + wm*32 + mt*16 + (lid>>2);
#pragma unroll
        for (int nt=0;nt<4;nt++){
            int gn0 = j0 + wn*32 + nt*8 + (lid&3)*2;
#pragma unroll
            for (int e=0;e<4;e++){
                int gi = gmr + (e>>1)*8;
                int gj = gn0 + (e&1);
                if (gj >= Nc) continue;
                float v = acc[mt][nt][e];
                long cidx = (long)b*sC_ + (long)gi*ldc + gj;
                if (EPI==0){ if (bias) v += bias[gj]; }
                else if (EPI==1){ v += bias[gj]; v += res[cidx]; }
                else if (EPI==2){ v += bias[gj]; v = 0.5f*v*(1.f+erff(v*0.70710678f)); }
                else if (EPI==3){ v = v*scale + (tm[b*Nq+gj]-1.f)*10000.f; }
                else if (EPI==4){ v = v + (tm[b*Nq+gi]*tm[b*Nq+gj]-1.f)*10000.f; }
                else if (EPI==5){ v = fmaxf(v/st1[b*M+gi], 0.f) + res[cidx]; }
                else if (EPI==6){ v = v*tm[b*Nq+gi] + res[cidx]; }
                C[cidx] = v;
            }
        }
    }
}

// ---------------- softmax / stats ----------------
template<bool WRITE>
__global__ void __launch_bounds__(256)
softmax_row_k(float* __restrict__ S, float* __restrict__ rmax, float* __restrict__ rsum){
    long row = blockIdx.x;
    float* p = S + row*(long)Nq;
    int t = threadIdx.x;
    float v[4];
    float mx = -1e30f;
#pragma unroll
    for (int l=0;l<4;l++){ v[l]=p[t+l*256]; mx=fmaxf(mx,v[l]); }
    __shared__ float sm[8];
    mx = warp_red_max(mx);
    if ((t&31)==0) sm[t>>5]=mx;
    __syncthreads();
    float m2 = sm[0];
#pragma unroll
    for (int w=1;w<8;w++) m2 = fmaxf(m2, sm[w]);
    float s = 0.f;
#pragma unroll
    for (int l=0;l<4;l++){ v[l]=__expf(v[l]-m2); s+=v[l]; }
    __syncthreads();
    s = warp_red_sum(s);
    if ((t&31)==0) sm[t>>5]=s;
    __syncthreads();
    float st = 0.f;
#pragma unroll
    for (int w=0;w<8;w++) st += sm[w];
    if (WRITE){
        float inv = 1.f/st;
#pragma unroll
        for (int l=0;l<4;l++) p[t+l*256] = v[l]*inv;
    } else if (t==0){ rmax[row]=m2; rsum[row]=st; }
}

__global__ void __launch_bounds__(256)
colstats_part(const float* __restrict__ L, float* __restrict__ pmax, float* __restrict__ psum){
    int g  = blockIdx.x*256 + threadIdx.x;
    int ch = blockIdx.y;
    int b = g >> 10, m = g & 1023;
    const float* p = L + (long)b*Nq*Nq + m + (long)ch*(Nq/NCH)*Nq;
    float mx=-1e30f, s=0.f;
#pragma unroll 4
    for (int n=0;n<Nq/NCH;n++){
        float x = p[(long)n*Nq];
        if (x>mx){ s = s*__expf(mx-x) + 1.f; mx = x; }
        else       s += __expf(x-mx);
    }
    pmax[ch*BNr+g]=mx; psum[ch*BNr+g]=s;
}
__global__ void __launch_bounds__(256)
colstats_comb(const float* __restrict__ pmax, const float* __restrict__ psum,
              float* __restrict__ cmax, float* __restrict__ csum){
    int g = blockIdx.x*256 + threadIdx.x;
    float mx=-1e30f, s=0.f;
#pragma unroll
    for (int ch=0; ch<NCH; ch++){
        float m2=pmax[ch*BNr+g], s2=psum[ch*BNr+g];
        if (m2>mx){ s = s*__expf(mx-m2) + s2; mx = m2; }
        else        s += s2*__expf(m2-mx);
    }
    cmax[g]=mx; csum[g]=s;
}

// ---------------- dual normalize: P_row in place, P_col^T transposed ----------------
__global__ void __launch_bounds__(256)
normalize_dual(float* __restrict__ L, float* __restrict__ LT,
               const float* __restrict__ rmax, const float* __restrict__ rsum,
               const float* __restrict__ cmax, const float* __restrict__ csum){
    __shared__ float sm[32][33];
    int b = blockIdx.z;
    int i0 = blockIdx.y*32, j0 = blockIdx.x*32;
    int tx = threadIdx.x & 31, ty = threadIdx.x >> 5;
    float* Lb  = L  + (long)b*Nq*Nq;
    float* LTb = LT + (long)b*Nq*Nq;
    int gb = b*Nq;
#pragma unroll
    for (int p=0;p<4;p++){
        int ti = ty + p*8;
        int gi = i0+ti, gj = j0+tx;
        float l = Lb[(long)gi*Nq + gj];
        Lb[(long)gi*Nq + gj] = __expf(l - rmax[gb+gi]) / rsum[gb+gi];
        sm[ti][tx] = __expf(l - cmax[gb+gj]) / csum[gb+gj];
    }
    __syncthreads();
#pragma unroll
    for (int p=0;p<4;p++){
        int tj = ty + p*8;
        LTb[(long)(j0+tj)*Nq + i0 + tx] = sm[tx][tj];
    }
}

// ---------------- layernorm (1 warp / row, H=200) ----------------
__global__ void __launch_bounds__(32)
ln_k(const float* __restrict__ X, const float* __restrict__ g,
     const float* __restrict__ bt, float* __restrict__ Y){
    long row = blockIdx.x;
    const float* x = X + row*Hq;
    float* y = Y + row*Hq;
    int t = threadIdx.x;
    float v[7]; float s=0.f;
#pragma unroll
    for (int l=0;l<7;l++){ int c=t+l*32; v[l]=(c<Hq)?x[c]:0.f; s+=v[l]; }
    s = warp_red_sum(s);
    float mu = s*(1.f/Hq);
    float var = 0.f;
#pragma unroll
    for (int l=0;l<7;l++){ int c=t+l*32; if (c<Hq){ float d=v[l]-mu; var+=d*d; } }
    var = warp_red_sum(var)*(1.f/Hq);
    float r = rsqrtf(var + 1e-20f);
#pragma unroll
    for (int l=0;l<7;l++){ int c=t+l*32; if (c<Hq) y[c] = (v[l]-mu)*r*g[c]+bt[c]; }
}

// ---------------- adj + denom ----------------
__global__ void __launch_bounds__(256)
adj_k(const float* __restrict__ a1, const float* __restrict__ a2,
      float* __restrict__ adjo, float* __restrict__ den){
    long row = blockIdx.x;
    long base = row*(long)Nq;
    int t = threadIdx.x;
    float s = 0.f;
#pragma unroll
    for (int l=0;l<4;l++){
        int m = t+l*256;
        float v = fminf(a1[base+m]+a2[base+m], 1.f);
        adjo[base+m]=v; s+=v;
    }
    __shared__ float sm[8];
    s = warp_red_sum(s);
    if ((t&31)==0) sm[t>>5]=s;
    __syncthreads();
    if (t==0){
        float tot=0.f;
#pragma unroll
        for (int w=0;w<8;w++) tot+=sm[w];
        den[row]=tot+1e-7f;
    }
}

__global__ void init_k(const float* __restrict__ text, float* __restrict__ o1, float* __restrict__ o2){
    for (long i = blockIdx.x*256L + threadIdx.x; i < (long)BNr*Hq; i += (long)gridDim.x*256)
    { float v=text[i]; o1[i]=v; o2[i]=v; }
}

// ---------------- qkv weight/bias pack: [3][200][608] and [3][608] ----------------
__global__ void wpack_k(const float* __restrict__ qw, const float* __restrict__ kw,
                        const float* __restrict__ vw, const float* __restrict__ qb,
                        const float* __restrict__ kb, const float* __restrict__ vb,
                        float* __restrict__ wq, float* __restrict__ bq){
    const long tot = 3L*Hq*LQ;
    for (long x = blockIdx.x*256L + threadIdx.x; x < tot; x += (long)gridDim.x*256){
        int i = (int)(x / (Hq*LQ)); int rem = (int)(x % (Hq*LQ));
        int k = rem / LQ, n = rem % LQ;
        float v = 0.f;
        if      (n < 200) v = qw[((long)i*Hq + k)*Hq + n];
        else if (n < 400) v = kw[((long)i*Hq + k)*Hq + (n-200)];
        else if (n < 600) v = vw[((long)i*Hq + k)*Hq + (n-400)];
        wq[x] = v;
    }
    for (long x = blockIdx.x*256L + threadIdx.x; x < 3*LQ; x += (long)gridDim.x*256){
        int i = (int)(x / LQ), n = (int)(x % LQ);
        float v = 0.f;
        if      (n < 200) v = qb[i*Hq + n];
        else if (n < 400) v = kb[i*Hq + n-200];
        else if (n < 600) v = vb[i*Hq + n-400];
        bq[x] = v;
    }
}

// ---------------- host-side GEMM launcher ----------------
template<int BT,int EPI>
static void MG(const float*A,const float*Bm,float*C,int M,int Nc,int Kd,
               int lda,int ldb,int ldc,long sa,long sb,long sc_,int batch,
               const float*bias,const float*res,const float*st1,const float*tmv,float scale){
    dim3 grid((Nc+63)/64, M/128, batch);
    mma_k<BT,EPI><<<grid,256>>>(A,Bm,C,M,Nc,Kd,lda,ldb,ldc,sa,sb,sc_,bias,res,st1,tmv,scale);
}

extern "C" void kernel_launch(void* const* d_in, const int* in_sizes, int n_in,
                              void* d_out, int out_size)
{
    const float* text  = (const float*)d_in[0];
    const float* adj1  = (const float*)d_in[1];
    const float* adj2  = (const float*)d_in[2];
    const float* tmask = (const float*)d_in[5];
    const float* gcn_w = (const float*)d_in[6];
    const float* mut_w = (const float*)d_in[7];
    const float* qw=(const float*)d_in[8],  *qb=(const float*)d_in[9];
    const float* kw=(const float*)d_in[10], *kb=(const float*)d_in[11];
    const float* vw=(const float*)d_in[12], *vb=(const float*)d_in[13];
    const float* aw=(const float*)d_in[14], *ab=(const float*)d_in[15];
    const float* g1=(const float*)d_in[16], *b1=(const float*)d_in[17];
    const float* iw=(const float*)d_in[18], *ib=(const float*)d_in[19];
    const float* ow=(const float*)d_in[20], *ob=(const float*)d_in[21];
    const float* g2=(const float*)d_in[22], *b2=(const float*)d_in[23];

    float* out  = (float*)d_out;
    float* adjo = out + (long)BNr*Hq;     // adj output region

    void* p;
    cudaGetSymbolAddress(&p, g_outs);   float* outs=(float*)p;
    cudaGetSymbolAddress(&p, g_output); float* outp=(float*)p;
    cudaGetSymbolAddress(&p, g_bufA);   float* bA=(float*)p;
    cudaGetSymbolAddress(&p, g_bufB);   float* bB=(float*)p;
    cudaGetSymbolAddress(&p, g_bufC);   float* bC=(float*)p;
    cudaGetSymbolAddress(&p, g_scores); float* sc=(float*)p;
    cudaGetSymbolAddress(&p, g_scT);    float* scT=(float*)p;
    cudaGetSymbolAddress(&p, g_qkv);    float* qkvb=(float*)p;
    cudaGetSymbolAddress(&p, g_wqkv);   float* wq=(float*)p;
    cudaGetSymbolAddress(&p, g_bqkv);   float* bq=(float*)p;
    cudaGetSymbolAddress(&p, g_denom);  float* den=(float*)p;
    cudaGetSymbolAddress(&p, g_rmax);   float* rmax=(float*)p;
    cudaGetSymbolAddress(&p, g_rsum);   float* rsum=(float*)p;
    cudaGetSymbolAddress(&p, g_cmax);   float* cmax=(float*)p;
    cudaGetSymbolAddress(&p, g_csum);   float* csum=(float*)p;
    cudaGetSymbolAddress(&p, g_pmax);   float* pmax=(float*)p;
    cudaGetSymbolAddress(&p, g_psum);   float* psum=(float*)p;

    const long sNH = (long)Nq*Hq;
    const long sNN = (long)Nq*Nq;
    const long sNQ = (long)Nq*LQ;
    const float rscale = 1.0f/sqrtf((float)Hq);

    init_k<<<640,256>>>(text, outs, outp);
    adj_k<<<BNr,256>>>(adj1, adj2, adjo, den);
    wpack_k<<<640,256>>>(qw,kw,vw,qb,kb,vb, wq,bq);

    for (int i=0;i<3;i++){
        const float *wqi=wq + (long)i*Hq*LQ, *bqi=bq + i*LQ;
        const float *awi=aw+i*Hq*Hq, *abi=ab+i*Hq;
        const float *iwi=iw+i*Hq*Hq, *ibi=ib+i*Hq;
        const float *owi=ow+i*Hq*Hq, *obi=ob+i*Hq;
        const float *g1i=g1+i*Hq, *b1i=b1+i*Hq, *g2i=g2+i*Hq, *b2i=b2+i*Hq;

        // ---- BERT layer ----
        MG<0,0>(outs,wqi,qkvb, BNr,600,Hq, Hq,LQ,LQ, 0,0,0, 1, bqi,0,0,0,0.f);          // q|k|v fused
        MG<1,3>(qkvb, qkvb+200, sc, Nq,Nq,Hq, LQ,LQ,Nq, sNQ,sNQ,sNN, Bq, 0,0,0, tmask, rscale); // scores
        softmax_row_k<true><<<BNr,256>>>(sc, 0, 0);
        MG<0,0>(sc, qkvb+400, bA, Nq,Hq,Nq, Nq,LQ,Hq, sNN,sNQ,sNH, Bq, 0,0,0,0,0.f);    // ctx
        MG<0,1>(bA,awi,bB, BNr,Hq,Hq, Hq,Hq,Hq, 0,0,0, 1, abi, outs, 0,0,0.f);          // pre-LN1
        ln_k<<<BNr,32>>>(bB, g1i, b1i, bC);                                              // attn
        MG<0,2>(bC,iwi,bA, BNr,Hq,Hq, Hq,Hq,Hq, 0,0,0, 1, ibi,0,0,0,0.f);               // inter (gelu)
        MG<0,1>(bA,owi,bB, BNr,Hq,Hq, Hq,Hq,Hq, 0,0,0, 1, obi, bC, 0,0,0.f);            // pre-LN2
        ln_k<<<BNr,32>>>(bB, g2i, b2i, outs);                                            // outs updated

        // ---- GCN propagation ----
        MG<0,0>(outp,gcn_w,bA, BNr,Hq,Hq, Hq,Hq,Hq, 0,0,0, 1, 0,0,0,0,0.f);             // teout
        MG<0,5>(adjo,bA,bB, Nq,Hq,Nq, Nq,Hq,Hq, sNN,sNH,sNH, Bq, 0, outp, den, 0, 0.f);
        { float* t_=outp; outp=bB; bB=t_; }

        // ---- self-alignment ----
        MG<0,0>(outs,mut_w,bA, BNr,Hq,Hq, Hq,Hq,Hq, 0,0,0, 1, 0,0,0,0,0.f);             // mo
        MG<1,4>(bA,outp,sc, Nq,Nq,Hq, Hq,Hq,Nq, sNH,sNH,sNN, Bq, 0,0,0, tmask, 0.f);    // logit
        softmax_row_k<false><<<BNr,256>>>(sc, rmax, rsum);
        colstats_part<<<dim3(BNr/256,NCH),256>>>(sc, pmax, psum);
        colstats_comb<<<BNr/256,256>>>(pmax, psum, cmax, csum);
        normalize_dual<<<dim3(Nq/32,Nq/32,Bq),256>>>(sc, scT, rmax, rsum, cmax, csum);
        MG<0,6>(sc,  outp, bC, Nq,Hq,Nq, Nq,Hq,Hq, sNN,sNH,sNH, Bq, 0, outs, 0, tmask, 0.f); // new_outs
        MG<0,6>(scT, outs, bB, Nq,Hq,Nq, Nq,Hq,Hq, sNN,sNH,sNH, Bq, 0, outp, 0, tmask, 0.f); // new_output
        { float* t_=outs; outs=bC; bC=t_; }
        { float* t_=outp; outp=bB; bB=t_; }
    }

    cudaMemcpyAsync(out, outs, (size_t)BNr*Hq*sizeof(float), cudaMemcpyDeviceToDevice);
}

// round 15
// speedup vs baseline: 1.1215x; 1.0465x over previous
#include <cuda_runtime.h>
#include <math.h>
#include <stdint.h>

#define Bq   8
#define Nq   1024
#define Hq   200
#define BNr  (Bq*Nq)
#define NCH  8
#define LQ   608

// ---------------- scratch (no allocs allowed) ----------------
__device__ float g_outs  [BNr*Hq];
__device__ float g_output[BNr*Hq];
__device__ float g_bufA  [BNr*Hq];
__device__ float g_bufB  [BNr*Hq];
__device__ float g_bufC  [BNr*Hq];
__device__ float g_scores[Bq*Nq*Nq];
__device__ float g_scT   [Bq*Nq*Nq];
__device__ float g_qkv   [(long)BNr*LQ];
__device__ float g_wqkv  [3L*Hq*LQ];
__device__ float g_bqkv  [3*LQ];
__device__ float g_denom [BNr];
__device__ float g_rmax  [BNr];
__device__ float g_rsum  [BNr];
__device__ float g_cmax  [BNr];
__device__ float g_csum  [BNr];
__device__ float g_pmax  [NCH*BNr];
__device__ float g_psum  [NCH*BNr];

// ---------------- generic helpers ----------------
__device__ __forceinline__ float warp_red_sum(float v){
#pragma unroll
    for (int o=16;o;o>>=1) v += __shfl_xor_sync(0xffffffffu, v, o);
    return v;
}
__device__ __forceinline__ float warp_red_max(float v){
#pragma unroll
    for (int o=16;o;o>>=1) v = fmaxf(v, __shfl_xor_sync(0xffffffffu, v, o));
    return v;
}

// ---------------- tensor-core primitives (baseline PTX, no 'a' features) ----------------
__device__ __forceinline__ uint32_t s2u(const void* p){
    uint32_t a;
    asm("{ .reg .u64 t; cvta.to.shared.u64 t, %1; cvt.u32.u64 %0, t; }" : "=r"(a) : "l"(p));
    return a;
}
__device__ __forceinline__ uint32_t bfp(float x0, float x1){
    uint32_t r;
    asm("cvt.rn.bf16x2.f32 %0, %1, %2;" : "=r"(r) : "f"(x1), "f"(x0));
    return r;
}
__device__ __forceinline__ float blo(uint32_t h){ return __uint_as_float(h<<16); }
__device__ __forceinline__ float bhi(uint32_t h){ return __uint_as_float(h & 0xFFFF0000u); }
__device__ __forceinline__ void ldmx4(uint32_t* r, uint32_t addr){
    asm volatile("ldmatrix.sync.aligned.m8n8.x4.shared.b16 {%0,%1,%2,%3}, [%4];"
        : "=r"(r[0]),"=r"(r[1]),"=r"(r[2]),"=r"(r[3]) : "r"(addr));
}
__device__ __forceinline__ void ldmx4t(uint32_t* r, uint32_t addr){
    asm volatile("ldmatrix.sync.aligned.m8n8.x4.trans.shared.b16 {%0,%1,%2,%3}, [%4];"
        : "=r"(r[0]),"=r"(r[1]),"=r"(r[2]),"=r"(r[3]) : "r"(addr));
}
__device__ __forceinline__ void mma16(float* d, const uint32_t* a, const uint32_t* b){
    asm volatile("mma.sync.aligned.m16n8k16.row.col.f32.bf16.bf16.f32 "
        "{%0,%1,%2,%3}, {%4,%5,%6,%7}, {%8,%9}, {%0,%1,%2,%3};"
        : "+f"(d[0]),"+f"(d[1]),"+f"(d[2]),"+f"(d[3])
        : "r"(a[0]),"r"(a[1]),"r"(a[2]),"r"(a[3]), "r"(b[0]),"r"(b[1]));
}
__device__ __forceinline__ int swz4(int row){ return ((row>>1) ^ (row>>3)) & 3; }

// ---------------- mma.sync bf16x3 GEMM (error-compensated) ----------------
// C[b,i,j] = epi( sum_k A[b,i,k] * Bop[b,k,j] ), near-fp32 via
//   x = xh + xl (bf16 split), C += Ah*Bh + Ah*Bl + Al*Bh  (drop Al*Bl ~2^-16)
// BT: 0 = B stored [Kd, Nc'] row-major -> smem [k][n] + ldmatrix.trans (R13-verified)
//     1 = B stored [Nc', Kd] row-major (native K-major, non-trans ldmatrix)
// EPI: 0 +bias(opt); 1 +bias+res; 2 gelu(+bias); 3 *scale+keymask(tm[gj]);
//      4 +pairmask; 5 relu(acc/st1[gi])+res; 6 acc*tm[gi]+res
// Requires M%128==0, Kd%4==0, lda/ldb%4==0, bases 16B-aligned; BT=0 also j0%8==0.
template<int BT,int EPI>
__global__ void __launch_bounds__(256,2)
mma_k(const float* __restrict__ A, const float* __restrict__ Bm, float* __restrict__ C,
      int M, int Nc, int Kd, int lda, int ldb, int ldc,
      long sA_, long sB_, long sC_,
      const float* __restrict__ bias, const float* __restrict__ res,
      const float* __restrict__ st1, const float* __restrict__ tm, float scale)
{
    // A planes: [buf][pl][128 rows * 64B] ; B planes: 4KB each:
    //   BT=1: [n row][64B of k]  BT=0: [k row][128B of n]
    __shared__ __align__(16) char sAm[2][2][128*64];   // 32 KB
    __shared__ __align__(16) char sBm[2][2][4096];     // 16 KB
    const int b  = blockIdx.z;
    const int i0 = blockIdx.y*128, j0 = blockIdx.x*64;
    const int tid = threadIdx.x, lid = tid&31, wid = tid>>5;
    const int wm = wid&3, wn = wid>>2;
    const float* Ab = A + (long)b*sA_;
    const float* Bb = Bm + (long)b*sB_;

    float acc[2][4][4];
#pragma unroll
    for (int mt=0;mt<2;mt++)
#pragma unroll
        for (int nt=0;nt<4;nt++)
#pragma unroll
            for (int e=0;e<4;e++) acc[mt][nt][e]=0.f;

    float4 ra[4];      // A staging: 128 rows x 32 k / 256 thr
    float4 rb1[2];     // B staging BT=1
    float4 rbt[2];     // B staging BT=0: 8 n-contig of one k

    auto ldgA = [&](int k0){
#pragma unroll
        for (int p=0;p<4;p++){
            int s = tid + p*256; int row = s>>3, kq = s&7;
            int gk = k0 + kq*4;
            ra[p] = (gk+3 < Kd) ? *(const float4*)&Ab[(long)(i0+row)*lda + gk]
                                : make_float4(0.f,0.f,0.f,0.f);
        }
    };
    auto stsA = [&](int sel){
#pragma unroll
        for (int p=0;p<4;p++){
            int s = tid + p*256; int row = s>>3, kq = s&7;
            float4 v = ra[p];
            uint32_t h0 = bfp(v.x, v.y), h1 = bfp(v.z, v.w);
            uint32_t l0 = bfp(v.x - blo(h0), v.y - bhi(h0));
            uint32_t l1 = bfp(v.z - blo(h1), v.w - bhi(h1));
            int off = row*64 + ((((kq>>1) ^ swz4(row))&3)<<4) + (kq&1)*8;
            *(uint2*)(sAm[sel][0] + off) = make_uint2(h0, h1);
            *(uint2*)(sAm[sel][1] + off) = make_uint2(l0, l1);
        }
    };
    auto ldgB = [&](int k0){
        if (BT==1){
#pragma unroll
            for (int p=0;p<2;p++){
                int s = tid + p*256; int row = s>>3, kq = s&7;
                int gj = j0 + row, gk = k0 + kq*4;
                rb1[p] = (gj < Nc && gk+3 < Kd) ? *(const float4*)&Bb[(long)gj*ldb + gk]
                                                : make_float4(0.f,0.f,0.f,0.f);
            }
        } else {
            int n0 = (tid&7)*8, kk = tid>>3;
            int gk = k0 + kk;
            bool ko = gk < Kd;
            int gn = j0 + n0;
            rbt[0] = (ko && gn+3 < Nc) ? *(const float4*)&Bb[(long)gk*ldb + gn]
                                       : make_float4(0.f,0.f,0.f,0.f);
            rbt[1] = (ko && gn+7 < Nc) ? *(const float4*)&Bb[(long)gk*ldb + gn + 4]
                                       : make_float4(0.f,0.f,0.f,0.f);
        }
    };
    auto stsB = [&](int sel){
        if (BT==1){
#pragma unroll
            for (int p=0;p<2;p++){
                int s = tid + p*256; int row = s>>3, kq = s&7;
                float4 v = rb1[p];
                uint32_t h0 = bfp(v.x, v.y), h1 = bfp(v.z, v.w);
                uint32_t l0 = bfp(v.x - blo(h0), v.y - bhi(h0));
                uint32_t l1 = bfp(v.z - blo(h1), v.w - bhi(h1));
                int off = row*64 + ((((kq>>1) ^ swz4(row))&3)<<4) + (kq&1)*8;
                *(uint2*)(sBm[sel][0] + off) = make_uint2(h0, h1);
                *(uint2*)(sBm[sel][1] + off) = make_uint2(l0, l1);
            }
        } else {
            // [k][n] row-major: row kk (128B = 64 n), 16B group g = n0/8, swizzle g ^ (kk&7)
            int g = tid&7, kk = tid>>3;
            float4 v0 = rbt[0], v1 = rbt[1];
            uint32_t h0 = bfp(v0.x, v0.y), h1 = bfp(v0.z, v0.w);
            uint32_t h2 = bfp(v1.x, v1.y), h3 = bfp(v1.z, v1.w);
            uint32_t l0 = bfp(v0.x - blo(h0), v0.y - bhi(h0));
            uint32_t l1 = bfp(v0.z - blo(h1), v0.w - bhi(h1));
            uint32_t l2 = bfp(v1.x - blo(h2), v1.y - bhi(h2));
            uint32_t l3 = bfp(v1.z - blo(h3), v1.w - bhi(h3));
            int off = kk*128 + (((g ^ (kk&7))&7)<<4);
            *(uint4*)(sBm[sel][0] + off) = make_uint4(h0,h1,h2,h3);
            *(uint4*)(sBm[sel][1] + off) = make_uint4(l0,l1,l2,l3);
        }
    };

    // per-lane fragment constants
    int arow[2], aswz[2];
#pragma unroll
    for (int mt=0;mt<2;mt++){
        arow[mt] = wm*32 + mt*16 + (lid&7) + ((lid>>3)&1)*8;
        aswz[mt] = swz4(arow[mt]);
    }
    const int akg = lid>>4;
    int brow[2], bswz[2];
#pragma unroll
    for (int jp=0;jp<2;jp++){
        brow[jp] = wn*32 + jp*16 + ((lid>>4)&1)*8 + (lid&7);
        bswz[jp] = swz4(brow[jp]);
    }
    const int bkg = (lid>>3)&1;
    const int tkrow = (lid&7) + ((lid>>3)&1)*8;   // BT=0 trans: k-row base within k16
    const int tng  = wn*4 + (lid>>4);             // BT=0 trans: n-group base (+jp*2)
    uint32_t aB[2][2], bB[2][2];
#pragma unroll
    for (int s=0;s<2;s++)
#pragma unroll
        for (int pl=0;pl<2;pl++){
            aB[s][pl] = s2u(sAm[s][pl]);
            bB[s][pl] = s2u(sBm[s][pl]);
        }

    const int nch = (Kd + 31) >> 5;
    ldgA(0); ldgB(0);
    stsA(0); stsB(0);
    for (int c=0; c<nch; c++){
        __syncthreads();
        if (c+1 < nch){ ldgA((c+1)*32); ldgB((c+1)*32); }
        const int sel = c & 1;
#pragma unroll
        for (int ks=0; ks<2; ks++){
            uint32_t aoff[2], boff[2];
            uint32_t afh[2][4], afl[2][4], bfh[2][4], bfl[2][4];
            // hi fragments
#pragma unroll
            for (int mt=0;mt<2;mt++){
                aoff[mt] = (uint32_t)(arow[mt]*64 + ((((2*ks+akg) ^ aswz[mt])&3)<<4));
                ldmx4(afh[mt], aB[sel][0] + aoff[mt]);
            }
            if (BT==1){
#pragma unroll
                for (int jp=0;jp<2;jp++){
                    boff[jp] = (uint32_t)(brow[jp]*64 + ((((2*ks+bkg) ^ bswz[jp])&3)<<4));
                    ldmx4(bfh[jp], bB[sel][0] + boff[jp]);
                }
            } else {
#pragma unroll
                for (int jp=0;jp<2;jp++){
                    int krow = ks*16 + tkrow;
                    int ngrp = tng + jp*2;
                    boff[jp] = (uint32_t)(krow*128 + (((ngrp ^ (krow&7))&7)<<4));
                    ldmx4t(bfh[jp], bB[sel][0] + boff[jp]);
                }
            }
            // hi*hi while lo fragments load
#pragma unroll
            for (int mt=0;mt<2;mt++)
#pragma unroll
                for (int nt=0;nt<4;nt++)
                    mma16(acc[mt][nt], afh[mt], &bfh[nt>>1][(nt&1)*2]);
#pragma unroll
            for (int mt=0;mt<2;mt++) ldmx4(afl[mt], aB[sel][1] + aoff[mt]);
            if (BT==1){
#pragma unroll
                for (int jp=0;jp<2;jp++) ldmx4(bfl[jp], bB[sel][1] + boff[jp]);
            } else {
#pragma unroll
                for (int jp=0;jp<2;jp++) ldmx4t(bfl[jp], bB[sel][1] + boff[jp]);
            }
            // cross terms
#pragma unroll
            for (int mt=0;mt<2;mt++)
#pragma unroll
                for (int nt=0;nt<4;nt++){
                    mma16(acc[mt][nt], afh[mt], &bfl[nt>>1][(nt&1)*2]);
                    mma16(acc[mt][nt], afl[mt], &bfh[nt>>1][(nt&1)*2]);
                }
        }
        if (c+1 < nch){ stsA((c+1)&1); stsB((c+1)&1); }
    }

    // ---- epilogue ----
#pragma unroll
    for (int mt=0;mt<2;mt++){
        int gmr = i0 + wm*32 + mt*16 + (lid>>2);
#pragma unroll
        for (int nt=0;nt<4;nt++){
            int gn0 = j0 + wn*32 + nt*8 + (lid&3)*2;
#pragma unroll
            for (int e=0;e<4;e++){
                int gi = gmr + (e>>1)*8;
                int gj = gn0 + (e&1);
                if (gj >= Nc) continue;
                float v = acc[mt][nt][e];
                long cidx = (long)b*sC_ + (long)gi*ldc + gj;
                if (EPI==0){ if (bias) v += bias[gj]; }
                else if (EPI==1){ v += bias[gj]; v += res[cidx]; }
                else if (EPI==2){ v += bias[gj]; v = 0.5f*v*(1.f+erff(v*0.70710678f)); }
                else if (EPI==3){ v = v*scale + (tm[b*Nq+gj]-1.f)*10000.f; }
                else if (EPI==4){ v = v + (tm[b*Nq+gi]*tm[b*Nq+gj]-1.f)*10000.f; }
                else if (EPI==5){ v = fmaxf(v/st1[b*M+gi], 0.f) + res[cidx]; }
                else if (EPI==6){ v = v*tm[b*Nq+gi] + res[cidx]; }
                C[cidx] = v;
            }
        }
    }
}

// ---------------- softmax / stats ----------------
template<bool WRITE>
__global__ void __launch_bounds__(256)
softmax_row_k(float* __restrict__ S, float* __restrict__ rmax, float* __restrict__ rsum){
    long row = blockIdx.x;
    float* p = S + row*(long)Nq;
    int t = threadIdx.x;
    float v[4];
    float mx = -1e30f;
#pragma unroll
    for (int l=0;l<4;l++){ v[l]=p[t+l*256]; mx=fmaxf(mx,v[l]); }
    __shared__ float sm[8];
    mx = warp_red_max(mx);
    if ((t&31)==0) sm[t>>5]=mx;
    __syncthreads();
    float m2 = sm[0];
#pragma unroll
    for (int w=1;w<8;w++) m2 = fmaxf(m2, sm[w]);
    float s = 0.f;
#pragma unroll
    for (int l=0;l<4;l++){ v[l]=__expf(v[l]-m2); s+=v[l]; }
    __syncthreads();
    s = warp_red_sum(s);
    if ((t&31)==0) sm[t>>5]=s;
    __syncthreads();
    float st = 0.f;
#pragma unroll
    for (int w=0;w<8;w++) st += sm[w];
    if (WRITE){
        float inv = 1.f/st;
#pragma unroll
        for (int l=0;l<4;l++) p[t+l*256] = v[l]*inv;
    } else if (t==0){ rmax[row]=m2; rsum[row]=st; }
}

__global__ void __launch_bounds__(256)
colstats_part(const float* __restrict__ L, float* __restrict__ pmax, float* __restrict__ psum){
    int g  = blockIdx.x*256 + threadIdx.x;
    int ch = blockIdx.y;
    int b = g >> 10, m = g & 1023;
    const float* p = L + (long)b*Nq*Nq + m + (long)ch*(Nq/NCH)*Nq;
    float mx=-1e30f, s=0.f;
#pragma unroll 4
    for (int n=0;n<Nq/NCH;n++){
        float x = p[(long)n*Nq];
        if (x>mx){ s = s*__expf(mx-x) + 1.f; mx = x; }
        else       s += __expf(x-mx);
    }
    pmax[ch*BNr+g]=mx; psum[ch*BNr+g]=s;
}
__global__ void __launch_bounds__(256)
colstats_comb(const float* __restrict__ pmax, const float* __restrict__ psum,
              float* __restrict__ cmax, float* __restrict__ csum){
    int g = blockIdx.x*256 + threadIdx.x;
    float mx=-1e30f, s=0.f;
#pragma unroll
    for (int ch=0; ch<NCH; ch++){
        float m2=pmax[ch*BNr+g], s2=psum[ch*BNr+g];
        if (m2>mx){ s = s*__expf(mx-m2) + s2; mx = m2; }
        else        s += s2*__expf(m2-mx);
    }
    cmax[g]=mx; csum[g]=s;
}

// ---------------- dual normalize: P_row in place, P_col^T transposed ----------------
__global__ void __launch_bounds__(256)
normalize_dual(float* __restrict__ L, float* __restrict__ LT,
               const float* __restrict__ rmax, const float* __restrict__ rsum,
               const float* __restrict__ cmax, const float* __restrict__ csum){
    __shared__ float sm[32][33];
    int b = blockIdx.z;
    int i0 = blockIdx.y*32, j0 = blockIdx.x*32;
    int tx = threadIdx.x & 31, ty = threadIdx.x >> 5;
    float* Lb  = L  + (long)b*Nq*Nq;
    float* LTb = LT + (long)b*Nq*Nq;
    int gb = b*Nq;
#pragma unroll
    for (int p=0;p<4;p++){
        int ti = ty + p*8;
        int gi = i0+ti, gj = j0+tx;
        float l = Lb[(long)gi*Nq + gj];
        Lb[(long)gi*Nq + gj] = __expf(l - rmax[gb+gi]) / rsum[gb+gi];
        sm[ti][tx] = __expf(l - cmax[gb+gj]) / csum[gb+gj];
    }
    __syncthreads();
#pragma unroll
    for (int p=0;p<4;p++){
        int tj = ty + p*8;
        LTb[(long)(j0+tj)*Nq + i0 + tx] = sm[tx][tj];
    }
}

// ---------------- layernorm (1 warp / row, H=200) ----------------
__global__ void __launch_bounds__(32)
ln_k(const float* __restrict__ X, const float* __restrict__ g,
     const float* __restrict__ bt, float* __restrict__ Y){
    long row = blockIdx.x;
    const float* x = X + row*Hq;
    float* y = Y + row*Hq;
    int t = threadIdx.x;
    float v[7]; float s=0.f;
#pragma unroll
    for (int l=0;l<7;l++){ int c=t+l*32; v[l]=(c<Hq)?x[c]:0.f; s+=v[l]; }
    s = warp_red_sum(s);
    float mu = s*(1.f/Hq);
    float var = 0.f;
#pragma unroll
    for (int l=0;l<7;l++){ int c=t+l*32; if (c<Hq){ float d=v[l]-mu; var+=d*d; } }
    var = warp_red_sum(var)*(1.f/Hq);
    float r = rsqrtf(var + 1e-20f);
#pragma unroll
    for (int l=0;l<7;l++){ int c=t+l*32; if (c<Hq) y[c] = (v[l]-mu)*r*g[c]+bt[c]; }
}

// ---------------- adj + denom ----------------
__global__ void __launch_bounds__(256)
adj_k(const float* __restrict__ a1, const float* __restrict__ a2,
      float* __restrict__ adjo, float* __restrict__ den){
    long row = blockIdx.x;
    long base = row*(long)Nq;
    int t = threadIdx.x;
    float s = 0.f;
#pragma unroll
    for (int l=0;l<4;l++){
        int m = t+l*256;
        float v = fminf(a1[base+m]+a2[base+m], 1.f);
        adjo[base+m]=v; s+=v;
    }
    __shared__ float sm[8];
    s = warp_red_sum(s);
    if ((t&31)==0) sm[t>>5]=s;
    __syncthreads();
    if (t==0){
        float tot=0.f;
#pragma unroll
        for (int w=0;w<8;w++) tot+=sm[w];
        den[row]=tot+1e-7f;
    }
}

__global__ void init_k(const float* __restrict__ text, float* __restrict__ o1, float* __restrict__ o2){
    for (long i = blockIdx.x*256L + threadIdx.x; i < (long)BNr*Hq; i += (long)gridDim.x*256)
    { float v=text[i]; o1[i]=v; o2[i]=v; }
}

// ---------------- qkv weight/bias pack: [3][200][608] and [3][608] ----------------
__global__ void wpack_k(const float* __restrict__ qw, const float* __restrict__ kw,
                        const float* __restrict__ vw, const float* __restrict__ qb,
                        const float* __restrict__ kb, const float* __restrict__ vb,
                        float* __restrict__ wq, float* __restrict__ bq){
    const long tot = 3L*Hq*LQ;
    for (long x = blockIdx.x*256L + threadIdx.x; x < tot; x += (long)gridDim.x*256){
        int i = (int)(x / (Hq*LQ)); int rem = (int)(x % (Hq*LQ));
        int k = rem / LQ, n = rem % LQ;
        float v = 0.f;
        if      (n < 200) v = qw[((long)i*Hq + k)*Hq + n];
        else if (n < 400) v = kw[((long)i*Hq + k)*Hq + (n-200)];
        else if (n < 600) v = vw[((long)i*Hq + k)*Hq + (n-400)];
        wq[x] = v;
    }
    for (long x = blockIdx.x*256L + threadIdx.x; x < 3*LQ; x += (long)gridDim.x*256){
        int i = (int)(x / LQ), n = (int)(x % LQ);
        float v = 0.f;
        if      (n < 200) v = qb[i*Hq + n];
        else if (n < 400) v = kb[i*Hq + n-200];
        else if (n < 600) v = vb[i*Hq + n-400];
        bq[x] = v;
    }
}

// ---------------- host-side GEMM launcher ----------------
template<int BT,int EPI>
static void MG(const float*A,const float*Bm,float*C,int M,int Nc,int Kd,
               int lda,int ldb,int ldc,long sa,long sb,long sc_,int batch,
               const float*bias,const float*res,const float*st1,const float*tmv,float scale){
    dim3 grid((Nc+63)/64, M/128, batch);
    mma_k<BT,EPI><<<grid,256>>>(A,Bm,C,M,Nc,Kd,lda,ldb,ldc,sa,sb,sc_,bias,res,st1,tmv,scale);
}

extern "C" void kernel_launch(void* const* d_in, const int* in_sizes, int n_in,
                              void* d_out, int out_size)
{
    const float* text  = (const float*)d_in[0];
    const float* adj1  = (const float*)d_in[1];
    const float* adj2  = (const float*)d_in[2];
    const float* tmask = (const float*)d_in[5];
    const float* gcn_w = (const float*)d_in[6];
    const float* mut_w = (const float*)d_in[7];
    const float* qw=(const float*)d_in[8],  *qb=(const float*)d_in[9];
    const float* kw=(const float*)d_in[10], *kb=(const float*)d_in[11];
    const float* vw=(const float*)d_in[12], *vb=(const float*)d_in[13];
    const float* aw=(const float*)d_in[14], *ab=(const float*)d_in[15];
    const float* g1=(const float*)d_in[16], *b1=(const float*)d_in[17];
    const float* iw=(const float*)d_in[18], *ib=(const float*)d_in[19];
    const float* ow=(const float*)d_in[20], *ob=(const float*)d_in[21];
    const float* g2=(const float*)d_in[22], *b2=(const float*)d_in[23];

    float* out  = (float*)d_out;
    float* adjo = out + (long)BNr*Hq;     // adj output region

    void* p;
    cudaGetSymbolAddress(&p, g_outs);   float* outs=(float*)p;
    cudaGetSymbolAddress(&p, g_output); float* outp=(float*)p;
    cudaGetSymbolAddress(&p, g_bufA);   float* bA=(float*)p;
    cudaGetSymbolAddress(&p, g_bufB);   float* bB=(float*)p;
    cudaGetSymbolAddress(&p, g_bufC);   float* bC=(float*)p;
    cudaGetSymbolAddress(&p, g_scores); float* sc=(float*)p;
    cudaGetSymbolAddress(&p, g_scT);    float* scT=(float*)p;
    cudaGetSymbolAddress(&p, g_qkv);    float* qkvb=(float*)p;
    cudaGetSymbolAddress(&p, g_wqkv);   float* wq=(float*)p;
    cudaGetSymbolAddress(&p, g_bqkv);   float* bq=(float*)p;
    cudaGetSymbolAddress(&p, g_denom);  float* den=(float*)p;
    cudaGetSymbolAddress(&p, g_rmax);   float* rmax=(float*)p;
    cudaGetSymbolAddress(&p, g_rsum);   float* rsum=(float*)p;
    cudaGetSymbolAddress(&p, g_cmax);   float* cmax=(float*)p;
    cudaGetSymbolAddress(&p, g_csum);   float* csum=(float*)p;
    cudaGetSymbolAddress(&p, g_pmax);   float* pmax=(float*)p;
    cudaGetSymbolAddress(&p, g_psum);   float* psum=(float*)p;

    const long sNH = (long)Nq*Hq;
    const long sNN = (long)Nq*Nq;
    const long sNQ = (long)Nq*LQ;
    const float rscale = 1.0f/sqrtf((float)Hq);

    init_k<<<640,256>>>(text, outs, outp);
    adj_k<<<BNr,256>>>(adj1, adj2, adjo, den);
    wpack_k<<<640,256>>>(qw,kw,vw,qb,kb,vb, wq,bq);

    for (int i=0;i<3;i++){
        const float *wqi=wq + (long)i*Hq*LQ, *bqi=bq + i*LQ;
        const float *awi=aw+i*Hq*Hq, *abi=ab+i*Hq;
        const float *iwi=iw+i*Hq*Hq, *ibi=ib+i*Hq;
        const float *owi=ow+i*Hq*Hq, *obi=ob+i*Hq;
        const float *g1i=g1+i*Hq, *b1i=b1+i*Hq, *g2i=g2+i*Hq, *b2i=b2+i*Hq;

        // ---- BERT layer ----
        MG<0,0>(outs,wqi,qkvb, BNr,600,Hq, Hq,LQ,LQ, 0,0,0, 1, bqi,0,0,0,0.f);          // q|k|v fused
        MG<1,3>(qkvb, qkvb+200, sc, Nq,Nq,Hq, LQ,LQ,Nq, sNQ,sNQ,sNN, Bq, 0,0,0, tmask, rscale); // scores
        softmax_row_k<true><<<BNr,256>>>(sc, 0, 0);
        MG<0,0>(sc, qkvb+400, bA, Nq,Hq,Nq, Nq,LQ,Hq, sNN,sNQ,sNH, Bq, 0,0,0,0,0.f);    // ctx
        MG<0,1>(bA,awi,bB, BNr,Hq,Hq, Hq,Hq,Hq, 0,0,0, 1, abi, outs, 0,0,0.f);          // pre-LN1
        ln_k<<<BNr,32>>>(bB, g1i, b1i, bC);                                              // attn
        MG<0,2>(bC,iwi,bA, BNr,Hq,Hq, Hq,Hq,Hq, 0,0,0, 1, ibi,0,0,0,0.f);               // inter (gelu)
        MG<0,1>(bA,owi,bB, BNr,Hq,Hq, Hq,Hq,Hq, 0,0,0, 1, obi, bC, 0,0,0.f);            // pre-LN2
        ln_k<<<BNr,32>>>(bB, g2i, b2i, outs);                                            // outs updated

        // ---- GCN propagation ----
        MG<0,0>(outp,gcn_w,bA, BNr,Hq,Hq, Hq,Hq,Hq, 0,0,0, 1, 0,0,0,0,0.f);             // teout
        MG<0,5>(adjo,bA,bB, Nq,Hq,Nq, Nq,Hq,Hq, sNN,sNH,sNH, Bq, 0, outp, den, 0, 0.f);
        { float* t_=outp; outp=bB; bB=t_; }

        // ---- self-alignment ----
        MG<0,0>(outs,mut_w,bA, BNr,Hq,Hq, Hq,Hq,Hq, 0,0,0, 1, 0,0,0,0,0.f);             // mo
        MG<1,4>(bA,outp,sc, Nq,Nq,Hq, Hq,Hq,Nq, sNH,sNH,sNN, Bq, 0,0,0, tmask, 0.f);    // logit
        softmax_row_k<false><<<BNr,256>>>(sc, rmax, rsum);
        colstats_part<<<dim3(BNr/256,NCH),256>>>(sc, pmax, psum);
        colstats_comb<<<BNr/256,256>>>(pmax, psum, cmax, csum);
        normalize_dual<<<dim3(Nq/32,Nq/32,Bq),256>>>(sc, scT, rmax, rsum, cmax, csum);
        MG<0,6>(sc,  outp, bC, Nq,Hq,Nq, Nq,Hq,Hq, sNN,sNH,sNH, Bq, 0, outs, 0, tmask, 0.f); // new_outs
        MG<0,6>(scT, outs, bB, Nq,Hq,Nq, Nq,Hq,Hq, sNN,sNH,sNH, Bq, 0, outp, 0, tmask, 0.f); // new_output
        { float* t_=outs; outs=bC; bC=t_; }
        { float* t_=outp; outp=bB; bB=t_; }
    }

    cudaMemcpyAsync(out, outs, (size_t)BNr*Hq*sizeof(float), cudaMemcpyDeviceToDevice);
}

// round 16
// speedup vs baseline: 1.1484x; 1.0240x over previous
#include <cuda_runtime.h>
#include <math.h>
#include <stdint.h>

#define Bq   8
#define Nq   1024
#define Hq   200
#define BNr  (Bq*Nq)
#define NCH  8
#define LQ   608

// dynamic smem layout (bytes): A[buf][pl][half] 8KB blocks, then B[buf][pl][half] 4KB
#define A_BLK   8192
#define A_TOT   65536
#define B_BLK   4096
#define SM_TOT  (A_TOT + 32768)    // 96 KB

// ---------------- scratch (no allocs allowed) ----------------
__device__ float g_outs  [BNr*Hq];
__device__ float g_output[BNr*Hq];
__device__ float g_bufA  [BNr*Hq];
__device__ float g_bufB  [BNr*Hq];
__device__ float g_bufC  [BNr*Hq];
__device__ float g_scores[Bq*Nq*Nq];
__device__ float g_scT   [Bq*Nq*Nq];
__device__ float g_qkv   [(long)BNr*LQ];
__device__ float g_wqkv  [3L*Hq*LQ];
__device__ float g_bqkv  [3*LQ];
__device__ float g_denom [BNr];
__device__ float g_rmax  [BNr];
__device__ float g_rsum  [BNr];
__device__ float g_cmax  [BNr];
__device__ float g_csum  [BNr];
__device__ float g_pmax  [NCH*BNr];
__device__ float g_psum  [NCH*BNr];

// ---------------- generic helpers ----------------
__device__ __forceinline__ float warp_red_sum(float v){
#pragma unroll
    for (int o=16;o;o>>=1) v += __shfl_xor_sync(0xffffffffu, v, o);
    return v;
}
__device__ __forceinline__ float warp_red_max(float v){
#pragma unroll
    for (int o=16;o;o>>=1) v = fmaxf(v, __shfl_xor_sync(0xffffffffu, v, o));
    return v;
}

// ---------------- tensor-core primitives (baseline PTX, no 'a' features) ----------------
__device__ __forceinline__ uint32_t s2u(const void* p){
    uint32_t a;
    asm("{ .reg .u64 t; cvta.to.shared.u64 t, %1; cvt.u32.u64 %0, t; }" : "=r"(a) : "l"(p));
    return a;
}
__device__ __forceinline__ uint32_t bfp(float x0, float x1){
    uint32_t r;
    asm("cvt.rn.bf16x2.f32 %0, %1, %2;" : "=r"(r) : "f"(x1), "f"(x0));
    return r;
}
__device__ __forceinline__ float blo(uint32_t h){ return __uint_as_float(h<<16); }
__device__ __forceinline__ float bhi(uint32_t h){ return __uint_as_float(h & 0xFFFF0000u); }
__device__ __forceinline__ void ldmx4(uint32_t* r, uint32_t addr){
    asm volatile("ldmatrix.sync.aligned.m8n8.x4.shared.b16 {%0,%1,%2,%3}, [%4];"
        : "=r"(r[0]),"=r"(r[1]),"=r"(r[2]),"=r"(r[3]) : "r"(addr));
}
__device__ __forceinline__ void ldmx4t(uint32_t* r, uint32_t addr){
    asm volatile("ldmatrix.sync.aligned.m8n8.x4.trans.shared.b16 {%0,%1,%2,%3}, [%4];"
        : "=r"(r[0]),"=r"(r[1]),"=r"(r[2]),"=r"(r[3]) : "r"(addr));
}
__device__ __forceinline__ void mma16(float* d, const uint32_t* a, const uint32_t* b){
    asm volatile("mma.sync.aligned.m16n8k16.row.col.f32.bf16.bf16.f32 "
        "{%0,%1,%2,%3}, {%4,%5,%6,%7}, {%8,%9}, {%0,%1,%2,%3};"
        : "+f"(d[0]),"+f"(d[1]),"+f"(d[2]),"+f"(d[3])
        : "r"(a[0]),"r"(a[1]),"r"(a[2]),"r"(a[3]), "r"(b[0]),"r"(b[1]));
}
__device__ __forceinline__ int swz4(int row){ return ((row>>1) ^ (row>>3)) & 3; }

// ---------------- mma.sync bf16x3 GEMM (error-compensated), K-chunk 64 ----------------
// C[b,i,j] = epi( sum_k A[b,i,k] * Bop[b,k,j] ), near-fp32 via
//   x = xh + xl (bf16 split), C += Ah*Bh + Ah*Bl + Al*Bh  (drop Al*Bl ~2^-16)
// BT: 0 = B stored [Kd, Nc'] row-major -> smem [k][n] + ldmatrix.trans
//     1 = B stored [Nc', Kd] row-major (native K-major, non-trans ldmatrix)
// EPI: 0 +bias(opt); 1 +bias+res; 2 gelu(+bias); 3 *scale+keymask(tm[gj]);
//      4 +pairmask; 5 relu(acc/st1[gi])+res; 6 acc*tm[gi]+res
// Requires M%128==0, Kd%4==0, lda/ldb%4==0, bases 16B-aligned; BT=0 also j0%8==0.
template<int BT,int EPI>
__global__ void __launch_bounds__(256,2)
mma_k(const float* __restrict__ A, const float* __restrict__ Bm, float* __restrict__ C,
      int M, int Nc, int Kd, int lda, int ldb, int ldc,
      long sA_, long sB_, long sC_,
      const float* __restrict__ bias, const float* __restrict__ res,
      const float* __restrict__ st1, const float* __restrict__ tm, float scale)
{
    extern __shared__ __align__(16) char smem[];
    const int b  = blockIdx.z;
    const int i0 = blockIdx.y*128, j0 = blockIdx.x*64;
    const int tid = threadIdx.x, lid = tid&31, wid = tid>>5;
    const int wm = wid&3, wn = wid>>2;
    const float* Ab = A + (long)b*sA_;
    const float* Bb = Bm + (long)b*sB_;
    const uint32_t smA = s2u(smem);           // A: buf*32K + pl*16K + half*8K
    const uint32_t smB = smA + A_TOT;         // B: buf*16K + pl*8K  + half*4K

    float acc[2][4][4];
#pragma unroll
    for (int mt=0;mt<2;mt++)
#pragma unroll
        for (int nt=0;nt<4;nt++)
#pragma unroll
            for (int e=0;e<4;e++) acc[mt][nt][e]=0.f;

    float4 ra[4];      // A staging: 128 rows x 32 k / 256 thr
    float4 rb1[2];     // B staging BT=1
    float4 rbt[2];     // B staging BT=0

    auto ldgA = [&](int k0){
#pragma unroll
        for (int p=0;p<4;p++){
            int s = tid + p*256; int row = s>>3, kq = s&7;
            int gk = k0 + kq*4;
            ra[p] = (gk+3 < Kd) ? *(const float4*)&Ab[(long)(i0+row)*lda + gk]
                                : make_float4(0.f,0.f,0.f,0.f);
        }
    };
    auto stsA = [&](int buf, int half){
        uint32_t base0 = smA + buf*32768 + half*A_BLK;
#pragma unroll
        for (int p=0;p<4;p++){
            int s = tid + p*256; int row = s>>3, kq = s&7;
            float4 v = ra[p];
            uint32_t h0 = bfp(v.x, v.y), h1 = bfp(v.z, v.w);
            uint32_t l0 = bfp(v.x - blo(h0), v.y - bhi(h0));
            uint32_t l1 = bfp(v.z - blo(h1), v.w - bhi(h1));
            uint32_t off = (uint32_t)(row*64 + ((((kq>>1) ^ swz4(row))&3)<<4) + (kq&1)*8);
            *(uint2*)(smem + (base0 - smA) + off)          = make_uint2(h0, h1);
            *(uint2*)(smem + (base0 - smA) + 16384 + off)  = make_uint2(l0, l1);
        }
    };
    auto ldgB = [&](int k0){
        if (BT==1){
#pragma unroll
            for (int p=0;p<2;p++){
                int s = tid + p*256; int row = s>>3, kq = s&7;
                int gj = j0 + row, gk = k0 + kq*4;
                rb1[p] = (gj < Nc && gk+3 < Kd) ? *(const float4*)&Bb[(long)gj*ldb + gk]
                                                : make_float4(0.f,0.f,0.f,0.f);
            }
        } else {
            int n0 = (tid&7)*8, kk = tid>>3;
            int gk = k0 + kk;
            bool ko = gk < Kd;
            int gn = j0 + n0;
            rbt[0] = (ko && gn+3 < Nc) ? *(const float4*)&Bb[(long)gk*ldb + gn]
                                       : make_float4(0.f,0.f,0.f,0.f);
            rbt[1] = (ko && gn+7 < Nc) ? *(const float4*)&Bb[(long)gk*ldb + gn + 4]
                                       : make_float4(0.f,0.f,0.f,0.f);
        }
    };
    auto stsB = [&](int buf, int half){
        uint32_t boff0 = A_TOT + buf*16384 + half*B_BLK;
        if (BT==1){
#pragma unroll
            for (int p=0;p<2;p++){
                int s = tid + p*256; int row = s>>3, kq = s&7;
                float4 v = rb1[p];
                uint32_t h0 = bfp(v.x, v.y), h1 = bfp(v.z, v.w);
                uint32_t l0 = bfp(v.x - blo(h0), v.y - bhi(h0));
                uint32_t l1 = bfp(v.z - blo(h1), v.w - bhi(h1));
                uint32_t off = (uint32_t)(row*64 + ((((kq>>1) ^ swz4(row))&3)<<4) + (kq&1)*8);
                *(uint2*)(smem + boff0 + off)        = make_uint2(h0, h1);
                *(uint2*)(smem + boff0 + 8192 + off) = make_uint2(l0, l1);
            }
        } else {
            int g = tid&7, kk = tid>>3;
            float4 v0 = rbt[0], v1 = rbt[1];
            uint32_t h0 = bfp(v0.x, v0.y), h1 = bfp(v0.z, v0.w);
            uint32_t h2 = bfp(v1.x, v1.y), h3 = bfp(v1.z, v1.w);
            uint32_t l0 = bfp(v0.x - blo(h0), v0.y - bhi(h0));
            uint32_t l1 = bfp(v0.z - blo(h1), v0.w - bhi(h1));
            uint32_t l2 = bfp(v1.x - blo(h2), v1.y - bhi(h2));
            uint32_t l3 = bfp(v1.z - blo(h3), v1.w - bhi(h3));
            uint32_t off = (uint32_t)(kk*128 + (((g ^ (kk&7))&7)<<4));
            *(uint4*)(smem + boff0 + off)        = make_uint4(h0,h1,h2,h3);
            *(uint4*)(smem + boff0 + 8192 + off) = make_uint4(l0,l1,l2,l3);
        }
    };

    // per-lane fragment constants
    int arow[2], aswz[2];
#pragma unroll
    for (int mt=0;mt<2;mt++){
        arow[mt] = wm*32 + mt*16 + (lid&7) + ((lid>>3)&1)*8;
        aswz[mt] = swz4(arow[mt]);
    }
    const int akg = lid>>4;
    int brow[2], bswz[2];
#pragma unroll
    for (int jp=0;jp<2;jp++){
        brow[jp] = wn*32 + jp*16 + ((lid>>4)&1)*8 + (lid&7);
        bswz[jp] = swz4(brow[jp]);
    }
    const int bkg = (lid>>3)&1;
    const int tkrow = (lid&7) + ((lid>>3)&1)*8;   // BT=0 trans: k-row base within k16
    const int tng  = wn*4 + (lid>>4);             // BT=0 trans: n-group base (+jp*2)

    // compute one K=32 sub-tile (2 k16 steps) from [buf][half]
    auto compute = [&](int buf, int half){
        uint32_t aH = smA + buf*32768 + half*A_BLK;
        uint32_t aL = aH + 16384;
        uint32_t bH = smB + buf*16384 + half*B_BLK;
        uint32_t bL = bH + 8192;
#pragma unroll
        for (int ks=0; ks<2; ks++){
            uint32_t aoff[2], boff[2];
            uint32_t afh[2][4], afl[2][4], bfh[2][4], bfl[2][4];
#pragma unroll
            for (int mt=0;mt<2;mt++){
                aoff[mt] = (uint32_t)(arow[mt]*64 + ((((2*ks+akg) ^ aswz[mt])&3)<<4));
                ldmx4(afh[mt], aH + aoff[mt]);
            }
            if (BT==1){
#pragma unroll
                for (int jp=0;jp<2;jp++){
                    boff[jp] = (uint32_t)(brow[jp]*64 + ((((2*ks+bkg) ^ bswz[jp])&3)<<4));
                    ldmx4(bfh[jp], bH + boff[jp]);
                }
            } else {
#pragma unroll
                for (int jp=0;jp<2;jp++){
                    int krow = ks*16 + tkrow;
                    int ngrp = tng + jp*2;
                    boff[jp] = (uint32_t)(krow*128 + (((ngrp ^ (krow&7))&7)<<4));
                    ldmx4t(bfh[jp], bH + boff[jp]);
                }
            }
#pragma unroll
            for (int mt=0;mt<2;mt++)
#pragma unroll
                for (int nt=0;nt<4;nt++)
                    mma16(acc[mt][nt], afh[mt], &bfh[nt>>1][(nt&1)*2]);
#pragma unroll
            for (int mt=0;mt<2;mt++) ldmx4(afl[mt], aL + aoff[mt]);
            if (BT==1){
#pragma unroll
                for (int jp=0;jp<2;jp++) ldmx4(bfl[jp], bL + boff[jp]);
            } else {
#pragma unroll
                for (int jp=0;jp<2;jp++) ldmx4t(bfl[jp], bL + boff[jp]);
            }
#pragma unroll
            for (int mt=0;mt<2;mt++)
#pragma unroll
                for (int nt=0;nt<4;nt++){
                    mma16(acc[mt][nt], afh[mt], &bfl[nt>>1][(nt&1)*2]);
                    mma16(acc[mt][nt], afl[mt], &bfh[nt>>1][(nt&1)*2]);
                }
        }
    };

    const int nch = (Kd + 63) >> 6;   // K-chunks of 64
    // prologue: stage chunk 0 (both halves) into buf 0
    ldgA(0); ldgB(0); stsA(0,0); stsB(0,0);
    ldgA(32); ldgB(32); stsA(0,1); stsB(0,1);
    for (int c=0; c<nch; c++){
        __syncthreads();
        const int sel = c & 1, nsel = sel ^ 1;
        const bool more = (c+1 < nch);
        if (more){ ldgA((c+1)*64); ldgB((c+1)*64); }     // loads for next chunk half0
        compute(sel, 0);
        if (more){
            stsA(nsel, 0); stsB(nsel, 0);
            ldgA((c+1)*64 + 32); ldgB((c+1)*64 + 32);    // next chunk half1
        }
        compute(sel, 1);
        if (more){ stsA(nsel, 1); stsB(nsel, 1); }
    }

    // ---- epilogue ----
#pragma unroll
    for (int mt=0;mt<2;mt++){
        int gmr = i0 + wm*32 + mt*16 + (lid>>2);
#pragma unroll
        for (int nt=0;nt<4;nt++){
            int gn0 = j0 + wn*32 + nt*8 + (lid&3)*2;
#pragma unroll
            for (int e=0;e<4;e++){
                int gi = gmr + (e>>1)*8;
                int gj = gn0 + (e&1);
                if (gj >= Nc) continue;
                float v = acc[mt][nt][e];
                long cidx = (long)b*sC_ + (long)gi*ldc + gj;
                if (EPI==0){ if (bias) v += bias[gj]; }
                else if (EPI==1){ v += bias[gj]; v += res[cidx]; }
                else if (EPI==2){ v += bias[gj]; v = 0.5f*v*(1.f+erff(v*0.70710678f)); }
                else if (EPI==3){ v = v*scale + (tm[b*Nq+gj]-1.f)*10000.f; }
                else if (EPI==4){ v = v + (tm[b*Nq+gi]*tm[b*Nq+gj]-1.f)*10000.f; }
                else if (EPI==5){ v = fmaxf(v/st1[b*M+gi], 0.f) + res[cidx]; }
                else if (EPI==6){ v = v*tm[b*Nq+gi] + res[cidx]; }
                C[cidx] = v;
            }
        }
    }
}

// ---------------- softmax / stats ----------------
template<bool WRITE>
__global__ void __launch_bounds__(256)
softmax_row_k(float* __restrict__ S, float* __restrict__ rmax, float* __restrict__ rsum){
    long row = blockIdx.x;
    float* p = S + row*(long)Nq;
    int t = threadIdx.x;
    float v[4];
    float mx = -1e30f;
#pragma unroll
    for (int l=0;l<4;l++){ v[l]=p[t+l*256]; mx=fmaxf(mx,v[l]); }
    __shared__ float sm[8];
    mx = warp_red_max(mx);
    if ((t&31)==0) sm[t>>5]=mx;
    __syncthreads();
    float m2 = sm[0];
#pragma unroll
    for (int w=1;w<8;w++) m2 = fmaxf(m2, sm[w]);
    float s = 0.f;
#pragma unroll
    for (int l=0;l<4;l++){ v[l]=__expf(v[l]-m2); s+=v[l]; }
    __syncthreads();
    s = warp_red_sum(s);
    if ((t&31)==0) sm[t>>5]=s;
    __syncthreads();
    float st = 0.f;
#pragma unroll
    for (int w=0;w<8;w++) st += sm[w];
    if (WRITE){
        float inv = 1.f/st;
#pragma unroll
        for (int l=0;l<4;l++) p[t+l*256] = v[l]*inv;
    } else if (t==0){ rmax[row]=m2; rsum[row]=st; }
}

__global__ void __launch_bounds__(256)
colstats_part(const float* __restrict__ L, float* __restrict__ pmax, float* __restrict__ psum){
    int g  = blockIdx.x*256 + threadIdx.x;
    int ch = blockIdx.y;
    int b = g >> 10, m = g & 1023;
    const float* p = L + (long)b*Nq*Nq + m + (long)ch*(Nq/NCH)*Nq;
    float mx=-1e30f, s=0.f;
#pragma unroll 4
    for (int n=0;n<Nq/NCH;n++){
        float x = p[(long)n*Nq];
        if (x>mx){ s = s*__expf(mx-x) + 1.f; mx = x; }
        else       s += __expf(x-mx);
    }
    pmax[ch*BNr+g]=mx; psum[ch*BNr+g]=s;
}
__global__ void __launch_bounds__(256)
colstats_comb(const float* __restrict__ pmax, const float* __restrict__ psum,
              float* __restrict__ cmax, float* __restrict__ csum){
    int g = blockIdx.x*256 + threadIdx.x;
    float mx=-1e30f, s=0.f;
#pragma unroll
    for (int ch=0; ch<NCH; ch++){
        float m2=pmax[ch*BNr+g], s2=psum[ch*BNr+g];
        if (m2>mx){ s = s*__expf(mx-m2) + s2; mx = m2; }
        else        s += s2*__expf(m2-mx);
    }
    cmax[g]=mx; csum[g]=s;
}

// ---------------- dual normalize: P_row in place, P_col^T transposed ----------------
__global__ void __launch_bounds__(256)
normalize_dual(float* __restrict__ L, float* __restrict__ LT,
               const float* __restrict__ rmax, const float* __restrict__ rsum,
               const float* __restrict__ cmax, const float* __restrict__ csum){
    __shared__ float sm[32][33];
    int b = blockIdx.z;
    int i0 = blockIdx.y*32, j0 = blockIdx.x*32;
    int tx = threadIdx.x & 31, ty = threadIdx.x >> 5;
    float* Lb  = L  + (long)b*Nq*Nq;
    float* LTb = LT + (long)b*Nq*Nq;
    int gb = b*Nq;
#pragma unroll
    for (int p=0;p<4;p++){
        int ti = ty + p*8;
        int gi = i0+ti, gj = j0+tx;
        float l = Lb[(long)gi*Nq + gj];
        Lb[(long)gi*Nq + gj] = __expf(l - rmax[gb+gi]) / rsum[gb+gi];
        sm[ti][tx] = __expf(l - cmax[gb+gj]) / csum[gb+gj];
    }
    __syncthreads();
#pragma unroll
    for (int p=0;p<4;p++){
        int tj = ty + p*8;
        LTb[(long)(j0+tj)*Nq + i0 + tx] = sm[tx][tj];
    }
}

// ---------------- layernorm (1 warp / row, H=200) ----------------
__global__ void __launch_bounds__(32)
ln_k(const float* __restrict__ X, const float* __restrict__ g,
     const float* __restrict__ bt, float* __restrict__ Y){
    long row = blockIdx.x;
    const float* x = X + row*Hq;
    float* y = Y + row*Hq;
    int t = threadIdx.x;
    float v[7]; float s=0.f;
#pragma unroll
    for (int l=0;l<7;l++){ int c=t+l*32; v[l]=(c<Hq)?x[c]:0.f; s+=v[l]; }
    s = warp_red_sum(s);
    float mu = s*(1.f/Hq);
    float var = 0.f;
#pragma unroll
    for (int l=0;l<7;l++){ int c=t+l*32; if (c<Hq){ float d=v[l]-mu; var+=d*d; } }
    var = warp_red_sum(var)*(1.f/Hq);
    float r = rsqrtf(var + 1e-20f);
#pragma unroll
    for (int l=0;l<7;l++){ int c=t+l*32; if (c<Hq) y[c] = (v[l]-mu)*r*g[c]+bt[c]; }
}

// ---------------- adj + denom ----------------
__global__ void __launch_bounds__(256)
adj_k(const float* __restrict__ a1, const float* __restrict__ a2,
      float* __restrict__ adjo, float* __restrict__ den){
    long row = blockIdx.x;
    long base = row*(long)Nq;
    int t = threadIdx.x;
    float s = 0.f;
#pragma unroll
    for (int l=0;l<4;l++){
        int m = t+l*256;
        float v = fminf(a1[base+m]+a2[base+m], 1.f);
        adjo[base+m]=v; s+=v;
    }
    __shared__ float sm[8];
    s = warp_red_sum(s);
    if ((t&31)==0) sm[t>>5]=s;
    __syncthreads();
    if (t==0){
        float tot=0.f;
#pragma unroll
        for (int w=0;w<8;w++) tot+=sm[w];
        den[row]=tot+1e-7f;
    }
}

__global__ void init_k(const float* __restrict__ text, float* __restrict__ o1, float* __restrict__ o2){
    for (long i = blockIdx.x*256L + threadIdx.x; i < (long)BNr*Hq; i += (long)gridDim.x*256)
    { float v=text[i]; o1[i]=v; o2[i]=v; }
}

// ---------------- qkv weight/bias pack: [3][200][608] and [3][608] ----------------
__global__ void wpack_k(const float* __restrict__ qw, const float* __restrict__ kw,
                        const float* __restrict__ vw, const float* __restrict__ qb,
                        const float* __restrict__ kb, const float* __restrict__ vb,
                        float* __restrict__ wq, float* __restrict__ bq){
    const long tot = 3L*Hq*LQ;
    for (long x = blockIdx.x*256L + threadIdx.x; x < tot; x += (long)gridDim.x*256){
        int i = (int)(x / (Hq*LQ)); int rem = (int)(x % (Hq*LQ));
        int k = rem / LQ, n = rem % LQ;
        float v = 0.f;
        if      (n < 200) v = qw[((long)i*Hq + k)*Hq + n];
        else if (n < 400) v = kw[((long)i*Hq + k)*Hq + (n-200)];
        else if (n < 600) v = vw[((long)i*Hq + k)*Hq + (n-400)];
        wq[x] = v;
    }
    for (long x = blockIdx.x*256L + threadIdx.x; x < 3*LQ; x += (long)gridDim.x*256){
        int i = (int)(x / LQ), n = (int)(x % LQ);
        float v = 0.f;
        if      (n < 200) v = qb[i*Hq + n];
        else if (n < 400) v = kb[i*Hq + n-200];
        else if (n < 600) v = vb[i*Hq + n-400];
        bq[x] = v;
    }
}

// ---------------- host-side GEMM launcher ----------------
template<int BT,int EPI>
static void MG(const float*A,const float*Bm,float*C,int M,int Nc,int Kd,
               int lda,int ldb,int ldc,long sa,long sb,long sc_,int batch,
               const float*bias,const float*res,const float*st1,const float*tmv,float scale){
    static bool cfg = false;
    if (!cfg){
        cudaFuncSetAttribute(mma_k<BT,EPI>, cudaFuncAttributeMaxDynamicSharedMemorySize, SM_TOT);
        cfg = true;
    }
    dim3 grid((Nc+63)/64, M/128, batch);
    mma_k<BT,EPI><<<grid,256,SM_TOT>>>(A,Bm,C,M,Nc,Kd,lda,ldb,ldc,sa,sb,sc_,bias,res,st1,tmv,scale);
}

extern "C" void kernel_launch(void* const* d_in, const int* in_sizes, int n_in,
                              void* d_out, int out_size)
{
    const float* text  = (const float*)d_in[0];
    const float* adj1  = (const float*)d_in[1];
    const float* adj2  = (const float*)d_in[2];
    const float* tmask = (const float*)d_in[5];
    const float* gcn_w = (const float*)d_in[6];
    const float* mut_w = (const float*)d_in[7];
    const float* qw=(const float*)d_in[8],  *qb=(const float*)d_in[9];
    const float* kw=(const float*)d_in[10], *kb=(const float*)d_in[11];
    const float* vw=(const float*)d_in[12], *vb=(const float*)d_in[13];
    const float* aw=(const float*)d_in[14], *ab=(const float*)d_in[15];
    const float* g1=(const float*)d_in[16], *b1=(const float*)d_in[17];
    const float* iw=(const float*)d_in[18], *ib=(const float*)d_in[19];
    const float* ow=(const float*)d_in[20], *ob=(const float*)d_in[21];
    const float* g2=(const float*)d_in[22], *b2=(const float*)d_in[23];

    float* out  = (float*)d_out;
    float* adjo = out + (long)BNr*Hq;     // adj output region

    void* p;
    cudaGetSymbolAddress(&p, g_outs);   float* outs=(float*)p;
    cudaGetSymbolAddress(&p, g_output); float* outp=(float*)p;
    cudaGetSymbolAddress(&p, g_bufA);   float* bA=(float*)p;
    cudaGetSymbolAddress(&p, g_bufB);   float* bB=(float*)p;
    cudaGetSymbolAddress(&p, g_bufC);   float* bC=(float*)p;
    cudaGetSymbolAddress(&p, g_scores); float* sc=(float*)p;
    cudaGetSymbolAddress(&p, g_scT);    float* scT=(float*)p;
    cudaGetSymbolAddress(&p, g_qkv);    float* qkvb=(float*)p;
    cudaGetSymbolAddress(&p, g_wqkv);   float* wq=(float*)p;
    cudaGetSymbolAddress(&p, g_bqkv);   float* bq=(float*)p;
    cudaGetSymbolAddress(&p, g_denom);  float* den=(float*)p;
    cudaGetSymbolAddress(&p, g_rmax);   float* rmax=(float*)p;
    cudaGetSymbolAddress(&p, g_rsum);   float* rsum=(float*)p;
    cudaGetSymbolAddress(&p, g_cmax);   float* cmax=(float*)p;
    cudaGetSymbolAddress(&p, g_csum);   float* csum=(float*)p;
    cudaGetSymbolAddress(&p, g_pmax);   float* pmax=(float*)p;
    cudaGetSymbolAddress(&p, g_psum);   float* psum=(float*)p;

    const long sNH = (long)Nq*Hq;
    const long sNN = (long)Nq*Nq;
    const long sNQ = (long)Nq*LQ;
    const float rscale = 1.0f/sqrtf((float)Hq);

    init_k<<<640,256>>>(text, outs, outp);
    adj_k<<<BNr,256>>>(adj1, adj2, adjo, den);
    wpack_k<<<640,256>>>(qw,kw,vw,qb,kb,vb, wq,bq);

    for (int i=0;i<3;i++){
        const float *wqi=wq + (long)i*Hq*LQ, *bqi=bq + i*LQ;
        const float *awi=aw+i*Hq*Hq, *abi=ab+i*Hq;
        const float *iwi=iw+i*Hq*Hq, *ibi=ib+i*Hq;
        const float *owi=ow+i*Hq*Hq, *obi=ob+i*Hq;
        const float *g1i=g1+i*Hq, *b1i=b1+i*Hq, *g2i=g2+i*Hq, *b2i=b2+i*Hq;

        // ---- BERT layer ----
        MG<0,0>(outs,wqi,qkvb, BNr,600,Hq, Hq,LQ,LQ, 0,0,0, 1, bqi,0,0,0,0.f);          // q|k|v fused
        MG<1,3>(qkvb, qkvb+200, sc, Nq,Nq,Hq, LQ,LQ,Nq, sNQ,sNQ,sNN, Bq, 0,0,0, tmask, rscale); // scores
        softmax_row_k<true><<<BNr,256>>>(sc, 0, 0);
        MG<0,0>(sc, qkvb+400, bA, Nq,Hq,Nq, Nq,LQ,Hq, sNN,sNQ,sNH, Bq, 0,0,0,0,0.f);    // ctx
        MG<0,1>(bA,awi,bB, BNr,Hq,Hq, Hq,Hq,Hq, 0,0,0, 1, abi, outs, 0,0,0.f);          // pre-LN1
        ln_k<<<BNr,32>>>(bB, g1i, b1i, bC);                                              // attn
        MG<0,2>(bC,iwi,bA, BNr,Hq,Hq, Hq,Hq,Hq, 0,0,0, 1, ibi,0,0,0,0.f);               // inter (gelu)
        MG<0,1>(bA,owi,bB, BNr,Hq,Hq, Hq,Hq,Hq, 0,0,0, 1, obi, bC, 0,0,0.f);            // pre-LN2
        ln_k<<<BNr,32>>>(bB, g2i, b2i, outs);                                            // outs updated

        // ---- GCN propagation ----
        MG<0,0>(outp,gcn_w,bA, BNr,Hq,Hq, Hq,Hq,Hq, 0,0,0, 1, 0,0,0,0,0.f);             // teout
        MG<0,5>(adjo,bA,bB, Nq,Hq,Nq, Nq,Hq,Hq, sNN,sNH,sNH, Bq, 0, outp, den, 0, 0.f);
        { float* t_=outp; outp=bB; bB=t_; }

        // ---- self-alignment ----
        MG<0,0>(outs,mut_w,bA, BNr,Hq,Hq, Hq,Hq,Hq, 0,0,0, 1, 0,0,0,0,0.f);             // mo
        MG<1,4>(bA,outp,sc, Nq,Nq,Hq, Hq,Hq,Nq, sNH,sNH,sNN, Bq, 0,0,0, tmask, 0.f);    // logit
        softmax_row_k<false><<<BNr,256>>>(sc, rmax, rsum);
        colstats_part<<<dim3(BNr/256,NCH),256>>>(sc, pmax, psum);
        colstats_comb<<<BNr/256,256>>>(pmax, psum, cmax, csum);
        normalize_dual<<<dim3(Nq/32,Nq/32,Bq),256>>>(sc, scT, rmax, rsum, cmax, csum);
        MG<0,6>(sc,  outp, bC, Nq,Hq,Nq, Nq,Hq,Hq, sNN,sNH,sNH, Bq, 0, outs, 0, tmask, 0.f); // new_outs
        MG<0,6>(scT, outs, bB, Nq,Hq,Nq, Nq,Hq,Hq, sNN,sNH,sNH, Bq, 0, outp, 0, tmask, 0.f); // new_output
        { float* t_=outs; outs=bC; bC=t_; }
        { float* t_=outp; outp=bB; bB=t_; }
    }

    cudaMemcpyAsync(out, outs, (size_t)BNr*Hq*sizeof(float), cudaMemcpyDeviceToDevice);
}